// round 5
// baseline (speedup 1.0000x reference)
#include <cuda_runtime.h>
#include <cuda_bf16.h>
#include <cstdint>

#define N_NODES 20000
#define N_EDGES 640000
#define HID 256
#define KBIG 512
#define D_OP 140
#define D_EMB 64
#define D_CFG 52
#define LN_EPS 1e-5f

// ---------------- scratch (device globals; no allocation) ----------------
__device__ float g_x[N_NODES * HID];        // fp32 features (agg input)
__device__ float g_h[N_NODES * HID];        // GEMM output
__device__ float g_Ah[N_NODES * KBIG];      // tf32-hi A: cols 0-255 = x, 256-511 = agg
__device__ float g_Al[N_NODES * KBIG];      // tf32-lo A
__device__ float g_WBh[4 * KBIG * HID];     // concat [Wself;Wneigh] hi, per layer
__device__ float g_WBl[4 * KBIG * HID];
__device__ float g_W1h[HID * HID];
__device__ float g_W1l[HID * HID];
__device__ float g_W2h[HID * (HID / 2)];
__device__ float g_W2l[HID * (HID / 2)];
__device__ int   g_deg[N_NODES];
__device__ float g_invdeg[N_NODES];
__device__ int   g_rowstart[N_NODES + 1];
__device__ int   g_cursor[N_NODES];
__device__ int   g_csr[N_EDGES];

__device__ __forceinline__ unsigned f2tf32(float x) {
    unsigned r;
    asm("cvt.rna.tf32.f32 %0, %1;" : "=r"(r) : "f"(x));
    return r;
}

// ---------------- graph preprocessing ----------------
__global__ void zero_kernel() {
    int i = blockIdx.x * blockDim.x + threadIdx.x;
    if (i < N_NODES) { g_deg[i] = 0; g_cursor[i] = 0; }
}

__global__ void deg_kernel(const int* __restrict__ dst) {
    int e = blockIdx.x * blockDim.x + threadIdx.x;
    if (e < N_EDGES) atomicAdd(&g_deg[dst[e]], 1);
}

__global__ void scan_kernel() {
    __shared__ int partial[256];
    int tid = threadIdx.x;
    const int CH = (N_NODES + 255) / 256;
    int base = tid * CH;
    int s = 0;
    for (int i = 0; i < CH; i++) {
        int idx = base + i;
        if (idx < N_NODES) s += g_deg[idx];
    }
    partial[tid] = s;
    __syncthreads();
    for (int off = 1; off < 256; off <<= 1) {
        int v = 0;
        if (tid >= off) v = partial[tid - off];
        __syncthreads();
        partial[tid] += v;
        __syncthreads();
    }
    int run = (tid == 0) ? 0 : partial[tid - 1];
    for (int i = 0; i < CH; i++) {
        int idx = base + i;
        if (idx < N_NODES) {
            int d = g_deg[idx];
            g_rowstart[idx] = run;
            run += d;
            g_invdeg[idx] = 1.0f / fmaxf((float)d, 1.0f);
        }
    }
    if (tid == 255) g_rowstart[N_NODES] = run;
}

__global__ void fill_kernel(const int* __restrict__ src, const int* __restrict__ dst) {
    int e = blockIdx.x * blockDim.x + threadIdx.x;
    if (e < N_EDGES) {
        int d = dst[e];
        int pos = atomicAdd(&g_cursor[d], 1);
        g_csr[g_rowstart[d] + pos] = src[e];
    }
}

// ---------------- weight splitting (once per launch) ----------------
#define WTOT (4 * KBIG * HID + HID * HID + HID * (HID / 2))
__global__ void split_w_kernel(const float* __restrict__ Wself,
                               const float* __restrict__ Wneigh,
                               const float* __restrict__ W1,
                               const float* __restrict__ W2) {
    int i = blockIdx.x * blockDim.x + threadIdx.x;
    if (i >= WTOT) return;
    float v; float* dh; float* dl; int di;
    if (i < 4 * KBIG * HID) {
        int l = i >> 17;            // / (512*256)
        int rem = i & (KBIG * HID - 1);
        int k = rem >> 8, n = rem & 255;
        v = (k < HID) ? Wself[(l * HID + k) * HID + n]
                      : Wneigh[(l * HID + (k - HID)) * HID + n];
        dh = g_WBh; dl = g_WBl; di = i;
    } else if (i < 4 * KBIG * HID + HID * HID) {
        di = i - 4 * KBIG * HID;
        v = W1[di]; dh = g_W1h; dl = g_W1l;
    } else {
        di = i - (4 * KBIG * HID + HID * HID);
        v = W2[di]; dh = g_W2h; dl = g_W2l;
    }
    float hf = __uint_as_float(f2tf32(v));
    dh[di] = hf;
    dl[di] = __uint_as_float(f2tf32(v - hf));
}

// ---------------- input feature assembly (+ split into A) ----------------
__global__ void build_x_kernel(const float* __restrict__ op_feats,
                               const float* __restrict__ cfg,
                               const float* __restrict__ emb,
                               const float* __restrict__ fmean,
                               const float* __restrict__ fstd,
                               const int* __restrict__ op_ids) {
    int n = blockIdx.x;
    int c = threadIdx.x;
    float v;
    if (c < D_OP)               v = op_feats[n * D_OP + c];
    else if (c < D_OP + D_EMB)  v = emb[op_ids[n] * D_EMB + (c - D_OP)];
    else                        v = cfg[n * D_CFG + (c - D_OP - D_EMB)];
    float xv = (v - fmean[c]) / fstd[c];
    g_x[n * HID + c] = xv;
    float hf = __uint_as_float(f2tf32(xv));
    g_Ah[n * KBIG + c] = hf;
    g_Al[n * KBIG + c] = __uint_as_float(f2tf32(xv - hf));
}

// ---------------- neighbor mean aggregation (+ split into A cols 256-511) ----------------
__global__ __launch_bounds__(64) void agg_kernel() {
    int n = blockIdx.x;
    int t = threadIdx.x;
    int s0 = g_rowstart[n], s1 = g_rowstart[n + 1];
    const float4* __restrict__ xv = (const float4*)g_x;
    float4 acc = make_float4(0.f, 0.f, 0.f, 0.f);

    int j = s0;
    for (; j + 4 <= s1; j += 4) {
        int i0 = g_csr[j], i1 = g_csr[j + 1], i2 = g_csr[j + 2], i3 = g_csr[j + 3];
        float4 v0 = xv[i0 * (HID / 4) + t];
        float4 v1 = xv[i1 * (HID / 4) + t];
        float4 v2 = xv[i2 * (HID / 4) + t];
        float4 v3 = xv[i3 * (HID / 4) + t];
        acc.x += (v0.x + v1.x) + (v2.x + v3.x);
        acc.y += (v0.y + v1.y) + (v2.y + v3.y);
        acc.z += (v0.z + v1.z) + (v2.z + v3.z);
        acc.w += (v0.w + v1.w) + (v2.w + v3.w);
    }
    for (; j < s1; j++) {
        int s = g_csr[j];
        float4 v = xv[s * (HID / 4) + t];
        acc.x += v.x; acc.y += v.y; acc.z += v.z; acc.w += v.w;
    }
    float id = g_invdeg[n];
    float vv[4] = {acc.x * id, acc.y * id, acc.z * id, acc.w * id};
    float4 hh, ll;
    float* hp = (float*)&hh; float* lp = (float*)&ll;
#pragma unroll
    for (int i = 0; i < 4; i++) {
        float hf = __uint_as_float(f2tf32(vv[i]));
        hp[i] = hf;
        lp[i] = __uint_as_float(f2tf32(vv[i] - hf));
    }
    ((float4*)g_Ah)[n * (KBIG / 4) + 64 + t] = hh;
    ((float4*)g_Al)[n * (KBIG / 4) + 64 + t] = ll;
}

// ---------------- TF32 tensor-core GEMM (pre-split, cp.async double-buffered) ----------------
#define BM 128
#define BN 64
#define BK 32
#define A_STRIDE 36
#define B_STRIDE 72
#define AH_OFF 0
#define AL_OFF (BM * A_STRIDE)                        // 4608
#define BH_OFF (2 * BM * A_STRIDE)                    // 9216
#define BL_OFF (2 * BM * A_STRIDE + BK * B_STRIDE)    // 11520
#define STAGE_FLOATS (2 * BM * A_STRIDE + 2 * BK * B_STRIDE)  // 13824
#define GEMM_SMEM (2 * STAGE_FLOATS * 4)              // 110592 bytes

__device__ __forceinline__ uint32_t sm_u32(const void* p) {
    uint32_t a;
    asm("{ .reg .u64 t; cvta.to.shared.u64 t, %1; cvt.u32.u64 %0, t; }" : "=r"(a) : "l"(p));
    return a;
}

__device__ __forceinline__ void cp16(uint32_t d, const void* s) {
    asm volatile("cp.async.cg.shared.global [%0], [%1], 16;" :: "r"(d), "l"(s));
}
__device__ __forceinline__ void cp16z(uint32_t d, const void* s, int sz) {
    asm volatile("cp.async.cg.shared.global [%0], [%1], 16, %2;" :: "r"(d), "l"(s), "r"(sz));
}

__device__ __forceinline__ void mma_tf32(float* c, const unsigned* a, const unsigned* b) {
    asm volatile(
        "mma.sync.aligned.m16n8k8.row.col.f32.tf32.tf32.f32 "
        "{%0,%1,%2,%3}, {%4,%5,%6,%7}, {%8,%9}, {%0,%1,%2,%3};"
        : "+f"(c[0]), "+f"(c[1]), "+f"(c[2]), "+f"(c[3])
        : "r"(a[0]), "r"(a[1]), "r"(a[2]), "r"(a[3]), "r"(b[0]), "r"(b[1]));
}

__global__ __launch_bounds__(256) void gemm_ps_kernel(
    const float* __restrict__ Agh, const float* __restrict__ Agl,   // row stride KBIG
    const float* __restrict__ Bgh, const float* __restrict__ Bgl,   // row stride NC
    const float* __restrict__ bias, float* __restrict__ C,
    int K, int NC)
{
    extern __shared__ float smem[];
    uint32_t s_base = sm_u32(smem);

    int tid = threadIdx.x;
    int lane = tid & 31, wid = tid >> 5;
    int warp_m = wid & 3, warp_n = wid >> 2;
    int g = lane >> 2, tig = lane & 3;

    int row0 = blockIdx.x * BM;
    int col0 = blockIdx.y * BN;

    int am[4], ak[4];
#pragma unroll
    for (int r = 0; r < 4; r++) {
        int c = tid + 256 * r;          // 1024 chunks of 4 floats covering 128x32
        am[r] = c >> 3;
        ak[r] = (c & 7) * 4;
    }
    int bk[2], bn[2];
#pragma unroll
    for (int r = 0; r < 2; r++) {
        int c = tid + 256 * r;          // 512 chunks covering 32x64
        bk[r] = c >> 4;
        bn[r] = (c & 15) * 4;
    }

    float acc[2][4][4];
#pragma unroll
    for (int mt = 0; mt < 2; mt++)
#pragma unroll
        for (int nt = 0; nt < 4; nt++)
#pragma unroll
            for (int i = 0; i < 4; i++) acc[mt][nt][i] = 0.f;

    const int NIT = K / BK;

    auto ISSUE = [&](int it, int buf) {
        int k0 = it * BK;
        uint32_t st = s_base + buf * (STAGE_FLOATS * 4);
#pragma unroll
        for (int r = 0; r < 4; r++) {
            int gm = row0 + am[r];
            int cgm = (gm < N_NODES) ? gm : (N_NODES - 1);
            int sz = (gm < N_NODES) ? 16 : 0;
            long off = (long)cgm * KBIG + k0 + ak[r];
            uint32_t so = (am[r] * A_STRIDE + ak[r]) * 4;
            cp16z(st + AH_OFF * 4 + so, Agh + off, sz);
            cp16z(st + AL_OFF * 4 + so, Agl + off, sz);
        }
#pragma unroll
        for (int r = 0; r < 2; r++) {
            long off = (long)(k0 + bk[r]) * NC + col0 + bn[r];
            uint32_t so = (bk[r] * B_STRIDE + bn[r]) * 4;
            cp16(st + BH_OFF * 4 + so, Bgh + off);
            cp16(st + BL_OFF * 4 + so, Bgl + off);
        }
        asm volatile("cp.async.commit_group;");
    };

    auto COMPUTE = [&](int buf) {
        const float* Ah = smem + buf * STAGE_FLOATS + AH_OFF;
        const float* Al = smem + buf * STAGE_FLOATS + AL_OFF;
        const float* Bh = smem + buf * STAGE_FLOATS + BH_OFF;
        const float* Bl = smem + buf * STAGE_FLOATS + BL_OFF;
#pragma unroll
        for (int ks = 0; ks < BK / 8; ks++) {
            unsigned ah[2][4], al[2][4], bh[4][2], bl[4][2];
#pragma unroll
            for (int mt = 0; mt < 2; mt++) {
                int mrow = warp_m * 32 + mt * 16 + g;
                int kc = ks * 8 + tig;
                ah[mt][0] = __float_as_uint(Ah[mrow * A_STRIDE + kc]);
                ah[mt][1] = __float_as_uint(Ah[(mrow + 8) * A_STRIDE + kc]);
                ah[mt][2] = __float_as_uint(Ah[mrow * A_STRIDE + kc + 4]);
                ah[mt][3] = __float_as_uint(Ah[(mrow + 8) * A_STRIDE + kc + 4]);
                al[mt][0] = __float_as_uint(Al[mrow * A_STRIDE + kc]);
                al[mt][1] = __float_as_uint(Al[(mrow + 8) * A_STRIDE + kc]);
                al[mt][2] = __float_as_uint(Al[mrow * A_STRIDE + kc + 4]);
                al[mt][3] = __float_as_uint(Al[(mrow + 8) * A_STRIDE + kc + 4]);
            }
#pragma unroll
            for (int nt = 0; nt < 4; nt++) {
                int ncol = warp_n * 32 + nt * 8 + g;
                int kr = ks * 8 + tig;
                bh[nt][0] = __float_as_uint(Bh[kr * B_STRIDE + ncol]);
                bh[nt][1] = __float_as_uint(Bh[(kr + 4) * B_STRIDE + ncol]);
                bl[nt][0] = __float_as_uint(Bl[kr * B_STRIDE + ncol]);
                bl[nt][1] = __float_as_uint(Bl[(kr + 4) * B_STRIDE + ncol]);
            }
#pragma unroll
            for (int mt = 0; mt < 2; mt++)
#pragma unroll
                for (int nt = 0; nt < 4; nt++) {
                    mma_tf32(acc[mt][nt], ah[mt], bh[nt]);
                    mma_tf32(acc[mt][nt], al[mt], bh[nt]);
                    mma_tf32(acc[mt][nt], ah[mt], bl[nt]);
                }
        }
    };

    ISSUE(0, 0);
    int buf = 0;
    for (int it = 0; it < NIT; it++) {
        if (it + 1 < NIT) {
            ISSUE(it + 1, buf ^ 1);
            asm volatile("cp.async.wait_group 1;");
        } else {
            asm volatile("cp.async.wait_group 0;");
        }
        __syncthreads();
        COMPUTE(buf);
        __syncthreads();
        buf ^= 1;
    }

    // epilogue
#pragma unroll
    for (int nt = 0; nt < 4; nt++) {
        int gc = col0 + warp_n * 32 + nt * 8 + 2 * tig;
        float b0 = bias ? bias[gc] : 0.f;
        float b1 = bias ? bias[gc + 1] : 0.f;
#pragma unroll
        for (int mt = 0; mt < 2; mt++) {
            int gr0 = row0 + warp_m * 32 + mt * 16 + g;
            if (gr0 < N_NODES) {
                float2 o = make_float2(acc[mt][nt][0] + b0, acc[mt][nt][1] + b1);
                *(float2*)&C[gr0 * NC + gc] = o;
            }
            int gr1 = gr0 + 8;
            if (gr1 < N_NODES) {
                float2 o = make_float2(acc[mt][nt][2] + b0, acc[mt][nt][3] + b1);
                *(float2*)&C[gr1 * NC + gc] = o;
            }
        }
    }
}

// ---------------- LayerNorm + ReLU (+ optional split write into A) ----------------
__global__ void ln_relu_kernel(const float* __restrict__ in,
                               float* __restrict__ outF,       // may be null; stride D
                               float* __restrict__ outH,       // may be null; stride KBIG
                               float* __restrict__ outL,
                               const float* __restrict__ gamma, const float* __restrict__ beta,
                               int D) {
    int row = blockIdx.x;
    int t = threadIdx.x;
    float v = in[row * D + t];

    __shared__ float ws[8];
    int w = t >> 5, l = t & 31, nw = D >> 5;

    float s = v;
#pragma unroll
    for (int o = 16; o; o >>= 1) s += __shfl_xor_sync(0xFFFFFFFFu, s, o);
    if (l == 0) ws[w] = s;
    __syncthreads();
    float tot = 0.f;
    for (int i = 0; i < nw; i++) tot += ws[i];
    float mu = tot / (float)D;
    __syncthreads();

    float d = v - mu;
    float s2 = d * d;
#pragma unroll
    for (int o = 16; o; o >>= 1) s2 += __shfl_xor_sync(0xFFFFFFFFu, s2, o);
    if (l == 0) ws[w] = s2;
    __syncthreads();
    float tot2 = 0.f;
    for (int i = 0; i < nw; i++) tot2 += ws[i];
    float var = tot2 / (float)D;

    float y = fmaxf(d * rsqrtf(var + LN_EPS) * gamma[t] + beta[t], 0.f);
    if (outF) outF[row * D + t] = y;
    if (outH) {
        float hf = __uint_as_float(f2tf32(y));
        outH[row * KBIG + t] = hf;
        outL[row * KBIG + t] = __uint_as_float(f2tf32(y - hf));
    }
}

// ---------------- launch ----------------
extern "C" void kernel_launch(void* const* d_in, const int* in_sizes, int n_in,
                              void* d_out, int out_size) {
    const float* op_feats    = (const float*)d_in[0];
    const float* config_f    = (const float*)d_in[1];
    const float* embed_table = (const float*)d_in[2];
    const float* feat_mean   = (const float*)d_in[3];
    const float* feat_std    = (const float*)d_in[4];
    const float* Wself       = (const float*)d_in[5];
    const float* Wneigh      = (const float*)d_in[6];
    const float* bconv       = (const float*)d_in[7];
    const float* conv_gamma  = (const float*)d_in[8];
    const float* conv_beta   = (const float*)d_in[9];
    const float* W1          = (const float*)d_in[10];
    const float* g1          = (const float*)d_in[11];
    const float* b1          = (const float*)d_in[12];
    const float* W2          = (const float*)d_in[13];
    const float* g2          = (const float*)d_in[14];
    const float* b2          = (const float*)d_in[15];
    const int*   op_ids      = (const int*)d_in[16];
    const int*   src         = (const int*)d_in[17];
    const int*   dst         = (const int*)d_in[18];
    float* out = (float*)d_out;

    float *xp, *hp, *Ahp, *Alp, *WBh, *WBl, *W1h, *W1l, *W2h, *W2l;
    cudaGetSymbolAddress((void**)&xp, g_x);
    cudaGetSymbolAddress((void**)&hp, g_h);
    cudaGetSymbolAddress((void**)&Ahp, g_Ah);
    cudaGetSymbolAddress((void**)&Alp, g_Al);
    cudaGetSymbolAddress((void**)&WBh, g_WBh);
    cudaGetSymbolAddress((void**)&WBl, g_WBl);
    cudaGetSymbolAddress((void**)&W1h, g_W1h);
    cudaGetSymbolAddress((void**)&W1l, g_W1l);
    cudaGetSymbolAddress((void**)&W2h, g_W2h);
    cudaGetSymbolAddress((void**)&W2l, g_W2l);

    cudaFuncSetAttribute(gemm_ps_kernel,
                         cudaFuncAttributeMaxDynamicSharedMemorySize, GEMM_SMEM);

    zero_kernel<<<(N_NODES + 255) / 256, 256>>>();
    deg_kernel<<<(N_EDGES + 255) / 256, 256>>>(dst);
    scan_kernel<<<1, 256>>>();
    fill_kernel<<<(N_EDGES + 255) / 256, 256>>>(src, dst);
    split_w_kernel<<<(WTOT + 255) / 256, 256>>>(Wself, Wneigh, W1, W2);

    build_x_kernel<<<N_NODES, HID>>>(op_feats, config_f, embed_table,
                                     feat_mean, feat_std, op_ids);

    dim3 ggrid((N_NODES + BM - 1) / BM, HID / BN);        // 157 x 4
    dim3 ggrid2((N_NODES + BM - 1) / BM, (HID / 2) / BN); // 157 x 2

    for (int i = 0; i < 4; i++) {
        agg_kernel<<<N_NODES, 64>>>();
        gemm_ps_kernel<<<ggrid, 256, GEMM_SMEM>>>(
            Ahp, Alp, WBh + i * KBIG * HID, WBl + i * KBIG * HID,
            bconv + i * HID, hp, KBIG, HID);
        ln_relu_kernel<<<N_NODES, HID>>>(hp, xp, Ahp, Alp,
                                         conv_gamma + i * HID, conv_beta + i * HID, HID);
    }

    gemm_ps_kernel<<<ggrid, 256, GEMM_SMEM>>>(Ahp, Alp, W1h, W1l, nullptr, hp, HID, HID);
    ln_relu_kernel<<<N_NODES, HID>>>(hp, nullptr, Ahp, Alp, g1, b1, HID);

    gemm_ps_kernel<<<ggrid2, 256, GEMM_SMEM>>>(Ahp, Alp, W2h, W2l, nullptr, hp, HID, HID / 2);
    ln_relu_kernel<<<N_NODES, HID / 2>>>(hp, out, nullptr, nullptr, g2, b2, HID / 2);
}

// round 6
// speedup vs baseline: 1.1231x; 1.1231x over previous
#include <cuda_runtime.h>
#include <cuda_fp16.h>
#include <cuda_bf16.h>
#include <cstdint>

#define N_NODES 20000
#define N_EDGES 640000
#define HID 256
#define D_OP 140
#define D_EMB 64
#define D_CFG 52
#define LN_EPS 1e-5f

// ---------------- scratch (device globals; no allocation) ----------------
__device__ float  g_x[N_NODES * HID];      // fp32 features (GEMM A0)
__device__ __half g_x16[N_NODES * HID];    // fp16 shadow of x (agg gather source)
__device__ float  g_h[N_NODES * HID];      // GEMM output
__device__ float  g_agg[N_NODES * HID];    // mean-aggregated neighbor feats (GEMM A1)
__device__ int    g_deg[N_NODES];
__device__ float  g_invdeg[N_NODES];
__device__ int    g_rowstart[N_NODES + 1];
__device__ int    g_cursor[N_NODES];
__device__ int    g_csr[N_EDGES];

// ---------------- graph preprocessing ----------------
__global__ void zero_kernel() {
    int i = blockIdx.x * blockDim.x + threadIdx.x;
    if (i < N_NODES) { g_deg[i] = 0; g_cursor[i] = 0; }
}

__global__ void deg_kernel(const int* __restrict__ dst) {
    int e = blockIdx.x * blockDim.x + threadIdx.x;
    if (e < N_EDGES) atomicAdd(&g_deg[dst[e]], 1);
}

__global__ void scan_kernel() {
    __shared__ int partial[256];
    int tid = threadIdx.x;
    const int CH = (N_NODES + 255) / 256;
    int base = tid * CH;
    int s = 0;
    for (int i = 0; i < CH; i++) {
        int idx = base + i;
        if (idx < N_NODES) s += g_deg[idx];
    }
    partial[tid] = s;
    __syncthreads();
    for (int off = 1; off < 256; off <<= 1) {
        int v = 0;
        if (tid >= off) v = partial[tid - off];
        __syncthreads();
        partial[tid] += v;
        __syncthreads();
    }
    int run = (tid == 0) ? 0 : partial[tid - 1];
    for (int i = 0; i < CH; i++) {
        int idx = base + i;
        if (idx < N_NODES) {
            int d = g_deg[idx];
            g_rowstart[idx] = run;
            run += d;
            g_invdeg[idx] = 1.0f / fmaxf((float)d, 1.0f);
        }
    }
    if (tid == 255) g_rowstart[N_NODES] = run;
}

__global__ void fill_kernel(const int* __restrict__ src, const int* __restrict__ dst) {
    int e = blockIdx.x * blockDim.x + threadIdx.x;
    if (e < N_EDGES) {
        int d = dst[e];
        int pos = atomicAdd(&g_cursor[d], 1);
        g_csr[g_rowstart[d] + pos] = src[e];
    }
}

// ---------------- input feature assembly (fp32 + fp16 shadow) ----------------
__global__ void build_x_kernel(const float* __restrict__ op_feats,
                               const float* __restrict__ cfg,
                               const float* __restrict__ emb,
                               const float* __restrict__ fmean,
                               const float* __restrict__ fstd,
                               const int* __restrict__ op_ids) {
    int n = blockIdx.x;
    int c = threadIdx.x;
    float v;
    if (c < D_OP)               v = op_feats[n * D_OP + c];
    else if (c < D_OP + D_EMB)  v = emb[op_ids[n] * D_EMB + (c - D_OP)];
    else                        v = cfg[n * D_CFG + (c - D_OP - D_EMB)];
    float xv = (v - fmean[c]) / fstd[c];
    g_x[n * HID + c] = xv;
    g_x16[n * HID + c] = __float2half(xv);
}

// ---------------- neighbor mean aggregation: gather fp16, accumulate fp32 ----------------
__global__ __launch_bounds__(64) void agg_kernel() {
    int n = blockIdx.x;
    int t = threadIdx.x;   // 64 threads, each owns 4 channels (one uint2 of 4 halves)
    int s0 = g_rowstart[n], s1 = g_rowstart[n + 1];
    const uint2* __restrict__ xv = (const uint2*)g_x16;   // 64 uint2 per row

    float4 acc = make_float4(0.f, 0.f, 0.f, 0.f);

    int j = s0;
    for (; j + 4 <= s1; j += 4) {
        int i0 = g_csr[j], i1 = g_csr[j + 1], i2 = g_csr[j + 2], i3 = g_csr[j + 3];
        uint2 r0 = xv[i0 * 64 + t];
        uint2 r1 = xv[i1 * 64 + t];
        uint2 r2 = xv[i2 * 64 + t];
        uint2 r3 = xv[i3 * 64 + t];
#pragma unroll
        for (int q = 0; q < 4; q++) {
            uint2 r = (q == 0) ? r0 : (q == 1) ? r1 : (q == 2) ? r2 : r3;
            float2 a = __half22float2(*(const __half2*)&r.x);
            float2 b = __half22float2(*(const __half2*)&r.y);
            acc.x += a.x; acc.y += a.y; acc.z += b.x; acc.w += b.y;
        }
    }
    for (; j < s1; j++) {
        uint2 r = xv[g_csr[j] * 64 + t];
        float2 a = __half22float2(*(const __half2*)&r.x);
        float2 b = __half22float2(*(const __half2*)&r.y);
        acc.x += a.x; acc.y += a.y; acc.z += b.x; acc.w += b.y;
    }
    float id = g_invdeg[n];
    acc.x *= id; acc.y *= id; acc.z *= id; acc.w *= id;
    ((float4*)g_agg)[n * (HID / 4) + t] = acc;
}

// ---------------- TF32 tensor-core GEMM (tf32x3 compensated) — R2 version ----------------
#define BM 128
#define BN 64
#define BK 32
#define A_STRIDE 36
#define B_STRIDE 72

__device__ __forceinline__ unsigned f2tf32(float x) {
    unsigned r;
    asm("cvt.rna.tf32.f32 %0, %1;" : "=r"(r) : "f"(x));
    return r;
}

__device__ __forceinline__ void mma_tf32(float* c, const unsigned* a, const unsigned* b) {
    asm volatile(
        "mma.sync.aligned.m16n8k8.row.col.f32.tf32.tf32.f32 "
        "{%0,%1,%2,%3}, {%4,%5,%6,%7}, {%8,%9}, {%0,%1,%2,%3};"
        : "+f"(c[0]), "+f"(c[1]), "+f"(c[2]), "+f"(c[3])
        : "r"(a[0]), "r"(a[1]), "r"(a[2]), "r"(a[3]), "r"(b[0]), "r"(b[1]));
}

__global__ __launch_bounds__(256) void gemm_tf32_kernel(
    const float* __restrict__ A0, const float* __restrict__ A1,
    const float* __restrict__ B0, const float* __restrict__ B1,
    const float* __restrict__ bias, float* __restrict__ C,
    int K, int NC)
{
    extern __shared__ float smem[];
    float* Ah = smem;
    float* Al = Ah + BM * A_STRIDE;
    float* Bh = Al + BM * A_STRIDE;
    float* Bl = Bh + BK * B_STRIDE;

    int tid = threadIdx.x;
    int lane = tid & 31, wid = tid >> 5;
    int warp_m = wid & 3, warp_n = wid >> 2;
    int g = lane >> 2, tig = lane & 3;

    int row0 = blockIdx.x * BM;
    int col0 = blockIdx.y * BN;

    float acc[2][4][4];
#pragma unroll
    for (int mt = 0; mt < 2; mt++)
#pragma unroll
        for (int nt = 0; nt < 4; nt++)
#pragma unroll
            for (int i = 0; i < 4; i++) acc[mt][nt][i] = 0.f;

    for (int k0 = 0; k0 < K; k0 += BK) {
        const float* Asrc; int ka;
        const float* Bsrc; int kb0;
        if (k0 < HID) { Asrc = A0; ka = k0;       Bsrc = B0; kb0 = k0; }
        else          { Asrc = A1; ka = k0 - HID; Bsrc = B1; kb0 = k0 - HID; }

#pragma unroll
        for (int r = 0; r < 4; r++) {
            int idx = tid + 256 * r;
            int m = idx >> 3, k4 = (idx & 7) * 4;
            float4 v = make_float4(0.f, 0.f, 0.f, 0.f);
            int gm = row0 + m;
            if (gm < N_NODES) v = *(const float4*)&Asrc[gm * HID + ka + k4];
            float vv[4] = {v.x, v.y, v.z, v.w};
#pragma unroll
            for (int i = 0; i < 4; i++) {
                float hf = __uint_as_float(f2tf32(vv[i]));
                Ah[m * A_STRIDE + k4 + i] = hf;
                Al[m * A_STRIDE + k4 + i] = __uint_as_float(f2tf32(vv[i] - hf));
            }
        }
#pragma unroll
        for (int r = 0; r < 2; r++) {
            int idx = tid + 256 * r;
            int n4 = (idx & 15) * 4, kk = idx >> 4;
            float4 v = *(const float4*)&Bsrc[(kb0 + kk) * NC + col0 + n4];
            float vv[4] = {v.x, v.y, v.z, v.w};
#pragma unroll
            for (int i = 0; i < 4; i++) {
                float hf = __uint_as_float(f2tf32(vv[i]));
                Bh[kk * B_STRIDE + n4 + i] = hf;
                Bl[kk * B_STRIDE + n4 + i] = __uint_as_float(f2tf32(vv[i] - hf));
            }
        }
        __syncthreads();

#pragma unroll
        for (int ks = 0; ks < BK / 8; ks++) {
            unsigned ah[2][4], al[2][4], bh[4][2], bl[4][2];
#pragma unroll
            for (int mt = 0; mt < 2; mt++) {
                int mrow = warp_m * 32 + mt * 16 + g;
                int kc = ks * 8 + tig;
                ah[mt][0] = __float_as_uint(Ah[mrow * A_STRIDE + kc]);
                ah[mt][1] = __float_as_uint(Ah[(mrow + 8) * A_STRIDE + kc]);
                ah[mt][2] = __float_as_uint(Ah[mrow * A_STRIDE + kc + 4]);
                ah[mt][3] = __float_as_uint(Ah[(mrow + 8) * A_STRIDE + kc + 4]);
                al[mt][0] = __float_as_uint(Al[mrow * A_STRIDE + kc]);
                al[mt][1] = __float_as_uint(Al[(mrow + 8) * A_STRIDE + kc]);
                al[mt][2] = __float_as_uint(Al[mrow * A_STRIDE + kc + 4]);
                al[mt][3] = __float_as_uint(Al[(mrow + 8) * A_STRIDE + kc + 4]);
            }
#pragma unroll
            for (int nt = 0; nt < 4; nt++) {
                int ncol = warp_n * 32 + nt * 8 + g;
                int kr = ks * 8 + tig;
                bh[nt][0] = __float_as_uint(Bh[kr * B_STRIDE + ncol]);
                bh[nt][1] = __float_as_uint(Bh[(kr + 4) * B_STRIDE + ncol]);
                bl[nt][0] = __float_as_uint(Bl[kr * B_STRIDE + ncol]);
                bl[nt][1] = __float_as_uint(Bl[(kr + 4) * B_STRIDE + ncol]);
            }
#pragma unroll
            for (int mt = 0; mt < 2; mt++)
#pragma unroll
                for (int nt = 0; nt < 4; nt++) {
                    mma_tf32(acc[mt][nt], ah[mt], bh[nt]);
                    mma_tf32(acc[mt][nt], al[mt], bh[nt]);
                    mma_tf32(acc[mt][nt], ah[mt], bl[nt]);
                }
        }
        __syncthreads();
    }

#pragma unroll
    for (int nt = 0; nt < 4; nt++) {
        int gc = col0 + warp_n * 32 + nt * 8 + 2 * tig;
        float b0 = bias ? bias[gc] : 0.f;
        float b1 = bias ? bias[gc + 1] : 0.f;
#pragma unroll
        for (int mt = 0; mt < 2; mt++) {
            int gr0 = row0 + warp_m * 32 + mt * 16 + g;
            if (gr0 < N_NODES) {
                float2 o = make_float2(acc[mt][nt][0] + b0, acc[mt][nt][1] + b1);
                *(float2*)&C[gr0 * NC + gc] = o;
            }
            int gr1 = gr0 + 8;
            if (gr1 < N_NODES) {
                float2 o = make_float2(acc[mt][nt][2] + b0, acc[mt][nt][3] + b1);
                *(float2*)&C[gr1 * NC + gc] = o;
            }
        }
    }
}

#define GEMM_SMEM ((2 * BM * A_STRIDE + 2 * BK * B_STRIDE) * 4)

// ---------------- LayerNorm + ReLU (+ optional fp16 shadow write) ----------------
__global__ void ln_relu_kernel(const float* __restrict__ in,
                               float* __restrict__ outF,
                               __half* __restrict__ out16,
                               const float* __restrict__ gamma, const float* __restrict__ beta,
                               int D) {
    int row = blockIdx.x;
    int t = threadIdx.x;
    float v = in[row * D + t];

    __shared__ float ws[8];
    int w = t >> 5, l = t & 31, nw = D >> 5;

    float s = v;
#pragma unroll
    for (int o = 16; o; o >>= 1) s += __shfl_xor_sync(0xFFFFFFFFu, s, o);
    if (l == 0) ws[w] = s;
    __syncthreads();
    float tot = 0.f;
    for (int i = 0; i < nw; i++) tot += ws[i];
    float mu = tot / (float)D;
    __syncthreads();

    float d = v - mu;
    float s2 = d * d;
#pragma unroll
    for (int o = 16; o; o >>= 1) s2 += __shfl_xor_sync(0xFFFFFFFFu, s2, o);
    if (l == 0) ws[w] = s2;
    __syncthreads();
    float tot2 = 0.f;
    for (int i = 0; i < nw; i++) tot2 += ws[i];
    float var = tot2 / (float)D;

    float y = fmaxf(d * rsqrtf(var + LN_EPS) * gamma[t] + beta[t], 0.f);
    outF[row * D + t] = y;
    if (out16) out16[row * D + t] = __float2half(y);
}

// ---------------- launch ----------------
extern "C" void kernel_launch(void* const* d_in, const int* in_sizes, int n_in,
                              void* d_out, int out_size) {
    const float* op_feats    = (const float*)d_in[0];
    const float* config_f    = (const float*)d_in[1];
    const float* embed_table = (const float*)d_in[2];
    const float* feat_mean   = (const float*)d_in[3];
    const float* feat_std    = (const float*)d_in[4];
    const float* Wself       = (const float*)d_in[5];
    const float* Wneigh      = (const float*)d_in[6];
    const float* bconv       = (const float*)d_in[7];
    const float* conv_gamma  = (const float*)d_in[8];
    const float* conv_beta   = (const float*)d_in[9];
    const float* W1          = (const float*)d_in[10];
    const float* g1          = (const float*)d_in[11];
    const float* b1          = (const float*)d_in[12];
    const float* W2          = (const float*)d_in[13];
    const float* g2          = (const float*)d_in[14];
    const float* b2          = (const float*)d_in[15];
    const int*   op_ids      = (const int*)d_in[16];
    const int*   src         = (const int*)d_in[17];
    const int*   dst         = (const int*)d_in[18];
    float* out = (float*)d_out;

    float *xp, *hp, *aggp;
    __half* x16p;
    cudaGetSymbolAddress((void**)&xp, g_x);
    cudaGetSymbolAddress((void**)&hp, g_h);
    cudaGetSymbolAddress((void**)&aggp, g_agg);
    cudaGetSymbolAddress((void**)&x16p, g_x16);

    cudaFuncSetAttribute(gemm_tf32_kernel,
                         cudaFuncAttributeMaxDynamicSharedMemorySize, GEMM_SMEM);

    zero_kernel<<<(N_NODES + 255) / 256, 256>>>();
    deg_kernel<<<(N_EDGES + 255) / 256, 256>>>(dst);
    scan_kernel<<<1, 256>>>();
    fill_kernel<<<(N_EDGES + 255) / 256, 256>>>(src, dst);

    build_x_kernel<<<N_NODES, HID>>>(op_feats, config_f, embed_table,
                                     feat_mean, feat_std, op_ids);

    dim3 ggrid((N_NODES + BM - 1) / BM, HID / BN);        // 157 x 4
    dim3 ggrid2((N_NODES + BM - 1) / BM, (HID / 2) / BN); // 157 x 2

    for (int i = 0; i < 4; i++) {
        agg_kernel<<<N_NODES, 64>>>();
        gemm_tf32_kernel<<<ggrid, 256, GEMM_SMEM>>>(
            xp, aggp, Wself + i * HID * HID, Wneigh + i * HID * HID,
            bconv + i * HID, hp, 2 * HID, HID);
        // fp16 shadow needed only while another agg follows (i<3)
        ln_relu_kernel<<<N_NODES, HID>>>(hp, xp, (i < 3) ? x16p : (__half*)nullptr,
                                         conv_gamma + i * HID, conv_beta + i * HID, HID);
    }

    gemm_tf32_kernel<<<ggrid, 256, GEMM_SMEM>>>(xp, nullptr, W1, nullptr, nullptr, hp, HID, HID);
    ln_relu_kernel<<<N_NODES, HID>>>(hp, xp, nullptr, g1, b1, HID);

    gemm_tf32_kernel<<<ggrid2, 256, GEMM_SMEM>>>(xp, nullptr, W2, nullptr, nullptr, hp, HID, HID / 2);
    ln_relu_kernel<<<N_NODES, HID / 2>>>(hp, out, nullptr, g2, b2, HID / 2);
}

// round 7
// speedup vs baseline: 1.3438x; 1.1965x over previous
#include <cuda_runtime.h>
#include <cuda_fp16.h>
#include <cuda_bf16.h>
#include <cstdint>

#define N_NODES 20000
#define N_EDGES 640000
#define HID 256
#define KB2 512
#define D_OP 140
#define D_EMB 64
#define D_CFG 52
#define LN_EPS 1e-5f

// ---------------- scratch (device globals; no allocation) ----------------
__device__ __nv_bfloat16 g_Abh[N_NODES * KB2];   // A hi: cols 0-255 = x, 256-511 = agg
__device__ __nv_bfloat16 g_Abl[N_NODES * KB2];   // A lo
__device__ __half        g_x16[N_NODES * HID];   // fp16 shadow for agg gather
__device__ float         g_h[N_NODES * HID];     // GEMM output
__device__ __nv_bfloat16 g_WBh[4 * HID * KB2];   // [layer][n=256][k=512] transposed concat W
__device__ __nv_bfloat16 g_WBl[4 * HID * KB2];
__device__ __nv_bfloat16 g_W1h[HID * HID];       // [n=256][k=256]
__device__ __nv_bfloat16 g_W1l[HID * HID];
__device__ __nv_bfloat16 g_W2h[(HID / 2) * HID]; // [n=128][k=256]
__device__ __nv_bfloat16 g_W2l[(HID / 2) * HID];
__device__ int   g_deg[N_NODES];
__device__ float g_invdeg[N_NODES];
__device__ int   g_rowstart[N_NODES + 1];
__device__ int   g_cursor[N_NODES];
__device__ int   g_csr[N_EDGES];

__device__ __forceinline__ void bf16split(float v, __nv_bfloat16& h, __nv_bfloat16& l) {
    h = __float2bfloat16_rn(v);
    l = __float2bfloat16_rn(v - __bfloat162float(h));
}

// ---------------- graph preprocessing ----------------
__global__ void zero_kernel() {
    int i = blockIdx.x * blockDim.x + threadIdx.x;
    if (i < N_NODES) { g_deg[i] = 0; g_cursor[i] = 0; }
}

__global__ void deg_kernel(const int* __restrict__ dst) {
    int e = blockIdx.x * blockDim.x + threadIdx.x;
    if (e < N_EDGES) atomicAdd(&g_deg[dst[e]], 1);
}

__global__ void scan_kernel() {
    __shared__ int partial[256];
    int tid = threadIdx.x;
    const int CH = (N_NODES + 255) / 256;
    int base = tid * CH;
    int s = 0;
    for (int i = 0; i < CH; i++) {
        int idx = base + i;
        if (idx < N_NODES) s += g_deg[idx];
    }
    partial[tid] = s;
    __syncthreads();
    for (int off = 1; off < 256; off <<= 1) {
        int v = 0;
        if (tid >= off) v = partial[tid - off];
        __syncthreads();
        partial[tid] += v;
        __syncthreads();
    }
    int run = (tid == 0) ? 0 : partial[tid - 1];
    for (int i = 0; i < CH; i++) {
        int idx = base + i;
        if (idx < N_NODES) {
            int d = g_deg[idx];
            g_rowstart[idx] = run;
            run += d;
            g_invdeg[idx] = 1.0f / fmaxf((float)d, 1.0f);
        }
    }
    if (tid == 255) g_rowstart[N_NODES] = run;
}

__global__ void fill_kernel(const int* __restrict__ src, const int* __restrict__ dst) {
    int e = blockIdx.x * blockDim.x + threadIdx.x;
    if (e < N_EDGES) {
        int d = dst[e];
        int pos = atomicAdd(&g_cursor[d], 1);
        g_csr[g_rowstart[d] + pos] = src[e];
    }
}

// ---------------- weight transpose + bf16 split (once per launch) ----------------
#define W_LAYER (4 * HID * KB2)               // 524288
#define W_TOT (W_LAYER + HID * HID + (HID / 2) * HID)
__global__ void split_w_kernel(const float* __restrict__ Wself,
                               const float* __restrict__ Wneigh,
                               const float* __restrict__ W1,
                               const float* __restrict__ W2) {
    int i = blockIdx.x * blockDim.x + threadIdx.x;
    if (i >= W_TOT) return;
    float v; __nv_bfloat16* dh; __nv_bfloat16* dl; int di;
    if (i < W_LAYER) {
        int l = i >> 17;                   // / (256*512)
        int rem = i & (HID * KB2 - 1);
        int n = rem >> 9, k = rem & 511;   // target [n][k]
        v = (k < HID) ? Wself[(l * HID + k) * HID + n]
                      : Wneigh[(l * HID + (k - HID)) * HID + n];
        dh = g_WBh; dl = g_WBl; di = i;
    } else if (i < W_LAYER + HID * HID) {
        di = i - W_LAYER;
        int n = di >> 8, k = di & 255;
        v = W1[k * HID + n];
        dh = g_W1h; dl = g_W1l;
    } else {
        di = i - (W_LAYER + HID * HID);
        int n = di >> 8, k = di & 255;
        v = W2[k * (HID / 2) + n];
        dh = g_W2h; dl = g_W2l;
    }
    bf16split(v, dh[di], dl[di]);
}

// ---------------- input feature assembly ----------------
__global__ void build_x_kernel(const float* __restrict__ op_feats,
                               const float* __restrict__ cfg,
                               const float* __restrict__ emb,
                               const float* __restrict__ fmean,
                               const float* __restrict__ fstd,
                               const int* __restrict__ op_ids) {
    int n = blockIdx.x;
    int c = threadIdx.x;
    float v;
    if (c < D_OP)               v = op_feats[n * D_OP + c];
    else if (c < D_OP + D_EMB)  v = emb[op_ids[n] * D_EMB + (c - D_OP)];
    else                        v = cfg[n * D_CFG + (c - D_OP - D_EMB)];
    float xv = (v - fmean[c]) / fstd[c];
    bf16split(xv, g_Abh[n * KB2 + c], g_Abl[n * KB2 + c]);
    g_x16[n * HID + c] = __float2half(xv);
}

// ---------------- neighbor mean aggregation: fp16 gather, fp32 accum, bf16 split out ----------------
__global__ __launch_bounds__(64) void agg_kernel() {
    int n = blockIdx.x;
    int t = threadIdx.x;   // 64 threads x 4 channels
    int s0 = g_rowstart[n], s1 = g_rowstart[n + 1];
    const uint2* __restrict__ xv = (const uint2*)g_x16;

    float4 acc = make_float4(0.f, 0.f, 0.f, 0.f);

    int j = s0;
    for (; j + 4 <= s1; j += 4) {
        int i0 = g_csr[j], i1 = g_csr[j + 1], i2 = g_csr[j + 2], i3 = g_csr[j + 3];
        uint2 r0 = xv[i0 * 64 + t];
        uint2 r1 = xv[i1 * 64 + t];
        uint2 r2 = xv[i2 * 64 + t];
        uint2 r3 = xv[i3 * 64 + t];
#pragma unroll
        for (int q = 0; q < 4; q++) {
            uint2 r = (q == 0) ? r0 : (q == 1) ? r1 : (q == 2) ? r2 : r3;
            float2 a = __half22float2(*(const __half2*)&r.x);
            float2 b = __half22float2(*(const __half2*)&r.y);
            acc.x += a.x; acc.y += a.y; acc.z += b.x; acc.w += b.y;
        }
    }
    for (; j < s1; j++) {
        uint2 r = xv[g_csr[j] * 64 + t];
        float2 a = __half22float2(*(const __half2*)&r.x);
        float2 b = __half22float2(*(const __half2*)&r.y);
        acc.x += a.x; acc.y += a.y; acc.z += b.x; acc.w += b.y;
    }
    float id = g_invdeg[n];
    float vv[4] = {acc.x * id, acc.y * id, acc.z * id, acc.w * id};
    __nv_bfloat16 hh[4], ll[4];
#pragma unroll
    for (int i = 0; i < 4; i++) bf16split(vv[i], hh[i], ll[i]);
    // cols 256 + t*4 .. +3 of row n (8 bytes each)
    *(uint2*)&g_Abh[n * KB2 + HID + t * 4] = *(const uint2*)hh;
    *(uint2*)&g_Abl[n * KB2 + HID + t * 4] = *(const uint2*)ll;
}

// ---------------- bf16x3 tensor-core GEMM (pre-split operands) ----------------
// C[N_NODES, NC] = A[., K] @ B^T  where B given transposed [NC][ldb]
#define BM 128
#define BN 64
#define BK 32
#define AS 40   // halves per A smem row (80B, conflict-free fragment reads)
#define BS 40

__device__ __forceinline__ void mma_bf16(float* c, const uint32_t* a, const uint32_t* b) {
    asm volatile(
        "mma.sync.aligned.m16n8k16.row.col.f32.bf16.bf16.f32 "
        "{%0,%1,%2,%3}, {%4,%5,%6,%7}, {%8,%9}, {%0,%1,%2,%3};"
        : "+f"(c[0]), "+f"(c[1]), "+f"(c[2]), "+f"(c[3])
        : "r"(a[0]), "r"(a[1]), "r"(a[2]), "r"(a[3]), "r"(b[0]), "r"(b[1]));
}

__global__ __launch_bounds__(256) void gemm_bf16_kernel(
    const __nv_bfloat16* __restrict__ Agh, const __nv_bfloat16* __restrict__ Agl, int lda,
    const __nv_bfloat16* __restrict__ Bgh, const __nv_bfloat16* __restrict__ Bgl, int ldb,
    const float* __restrict__ bias, float* __restrict__ C, int K, int NC)
{
    __shared__ __align__(16) uint16_t Ash[BM * AS], Asl[BM * AS];
    __shared__ __align__(16) uint16_t Bsh[BN * BS], Bsl[BN * BS];

    int tid = threadIdx.x;
    int lane = tid & 31, wid = tid >> 5;
    int warp_m = wid & 3, warp_n = wid >> 2;       // 4 x 2 warps, 32x32 warp tile
    int g = lane >> 2, tig = lane & 3;

    int row0 = blockIdx.x * BM;
    int col0 = blockIdx.y * BN;

    float acc[2][4][4];
#pragma unroll
    for (int mt = 0; mt < 2; mt++)
#pragma unroll
        for (int nt = 0; nt < 4; nt++)
#pragma unroll
            for (int i = 0; i < 4; i++) acc[mt][nt][i] = 0.f;

    for (int k0 = 0; k0 < K; k0 += BK) {
        // A tile: 128x32 halves per array, float4 = 8 halves; 512 chunks, 2/thread
#pragma unroll
        for (int r = 0; r < 2; r++) {
            int idx = tid + 256 * r;
            int m = idx >> 2, k8 = (idx & 3) * 8;
            int gm = row0 + m;
            float4 vh = make_float4(0.f, 0.f, 0.f, 0.f), vl = vh;
            if (gm < N_NODES) {
                size_t off = (size_t)gm * lda + k0 + k8;
                vh = *(const float4*)&Agh[off];
                vl = *(const float4*)&Agl[off];
            }
            *(float4*)&Ash[m * AS + k8] = vh;
            *(float4*)&Asl[m * AS + k8] = vl;
        }
        // B tile: 64x32 halves per array; 256 chunks, 1/thread
        {
            int n = tid >> 2, k8 = (tid & 3) * 8;
            size_t off = (size_t)(col0 + n) * ldb + k0 + k8;
            *(float4*)&Bsh[n * BS + k8] = *(const float4*)&Bgh[off];
            *(float4*)&Bsl[n * BS + k8] = *(const float4*)&Bgl[off];
        }
        __syncthreads();

#pragma unroll
        for (int ks = 0; ks < 2; ks++) {          // two k16 steps per BK=32
            int kb = ks * 16 + 2 * tig;
            uint32_t ah[2][4], al[2][4], bh[4][2], bl[4][2];
#pragma unroll
            for (int mt = 0; mt < 2; mt++) {
                int mrow = warp_m * 32 + mt * 16 + g;
                ah[mt][0] = *(const uint32_t*)&Ash[mrow * AS + kb];
                ah[mt][1] = *(const uint32_t*)&Ash[(mrow + 8) * AS + kb];
                ah[mt][2] = *(const uint32_t*)&Ash[mrow * AS + kb + 8];
                ah[mt][3] = *(const uint32_t*)&Ash[(mrow + 8) * AS + kb + 8];
                al[mt][0] = *(const uint32_t*)&Asl[mrow * AS + kb];
                al[mt][1] = *(const uint32_t*)&Asl[(mrow + 8) * AS + kb];
                al[mt][2] = *(const uint32_t*)&Asl[mrow * AS + kb + 8];
                al[mt][3] = *(const uint32_t*)&Asl[(mrow + 8) * AS + kb + 8];
            }
#pragma unroll
            for (int nt = 0; nt < 4; nt++) {
                int ncol = warp_n * 32 + nt * 8 + g;
                bh[nt][0] = *(const uint32_t*)&Bsh[ncol * BS + kb];
                bh[nt][1] = *(const uint32_t*)&Bsh[ncol * BS + kb + 8];
                bl[nt][0] = *(const uint32_t*)&Bsl[ncol * BS + kb];
                bl[nt][1] = *(const uint32_t*)&Bsl[ncol * BS + kb + 8];
            }
#pragma unroll
            for (int mt = 0; mt < 2; mt++)
#pragma unroll
                for (int nt = 0; nt < 4; nt++) {
                    mma_bf16(acc[mt][nt], ah[mt], bh[nt]);   // hi*hi
                    mma_bf16(acc[mt][nt], al[mt], bh[nt]);   // lo*hi
                    mma_bf16(acc[mt][nt], ah[mt], bl[nt]);   // hi*lo
                }
        }
        __syncthreads();
    }

    // epilogue (same C fragment layout as m16n8k8)
#pragma unroll
    for (int nt = 0; nt < 4; nt++) {
        int gc = col0 + warp_n * 32 + nt * 8 + 2 * tig;
        float b0 = bias ? bias[gc] : 0.f;
        float b1 = bias ? bias[gc + 1] : 0.f;
#pragma unroll
        for (int mt = 0; mt < 2; mt++) {
            int gr0 = row0 + warp_m * 32 + mt * 16 + g;
            if (gr0 < N_NODES) {
                float2 o = make_float2(acc[mt][nt][0] + b0, acc[mt][nt][1] + b1);
                *(float2*)&C[gr0 * NC + gc] = o;
            }
            int gr1 = gr0 + 8;
            if (gr1 < N_NODES) {
                float2 o = make_float2(acc[mt][nt][2] + b0, acc[mt][nt][3] + b1);
                *(float2*)&C[gr1 * NC + gc] = o;
            }
        }
    }
}

// ---------------- LayerNorm + ReLU (+ bf16 split / fp16 shadow / fp32 out) ----------------
__global__ void ln_relu_kernel(const float* __restrict__ in,
                               float* __restrict__ outF,
                               __nv_bfloat16* __restrict__ outH,
                               __nv_bfloat16* __restrict__ outL,
                               __half* __restrict__ out16,
                               const float* __restrict__ gamma, const float* __restrict__ beta,
                               int D) {
    int row = blockIdx.x;
    int t = threadIdx.x;
    float v = in[row * D + t];

    __shared__ float ws[8];
    int w = t >> 5, l = t & 31, nw = D >> 5;

    float s = v;
#pragma unroll
    for (int o = 16; o; o >>= 1) s += __shfl_xor_sync(0xFFFFFFFFu, s, o);
    if (l == 0) ws[w] = s;
    __syncthreads();
    float tot = 0.f;
    for (int i = 0; i < nw; i++) tot += ws[i];
    float mu = tot / (float)D;
    __syncthreads();

    float d = v - mu;
    float s2 = d * d;
#pragma unroll
    for (int o = 16; o; o >>= 1) s2 += __shfl_xor_sync(0xFFFFFFFFu, s2, o);
    if (l == 0) ws[w] = s2;
    __syncthreads();
    float tot2 = 0.f;
    for (int i = 0; i < nw; i++) tot2 += ws[i];
    float var = tot2 / (float)D;

    float y = fmaxf(d * rsqrtf(var + LN_EPS) * gamma[t] + beta[t], 0.f);
    if (outF) outF[row * D + t] = y;
    if (outH) bf16split(y, outH[row * KB2 + t], outL[row * KB2 + t]);
    if (out16) out16[row * D + t] = __float2half(y);
}

// ---------------- launch ----------------
extern "C" void kernel_launch(void* const* d_in, const int* in_sizes, int n_in,
                              void* d_out, int out_size) {
    const float* op_feats    = (const float*)d_in[0];
    const float* config_f    = (const float*)d_in[1];
    const float* embed_table = (const float*)d_in[2];
    const float* feat_mean   = (const float*)d_in[3];
    const float* feat_std    = (const float*)d_in[4];
    const float* Wself       = (const float*)d_in[5];
    const float* Wneigh      = (const float*)d_in[6];
    const float* bconv       = (const float*)d_in[7];
    const float* conv_gamma  = (const float*)d_in[8];
    const float* conv_beta   = (const float*)d_in[9];
    const float* W1          = (const float*)d_in[10];
    const float* g1          = (const float*)d_in[11];
    const float* b1          = (const float*)d_in[12];
    const float* W2          = (const float*)d_in[13];
    const float* g2          = (const float*)d_in[14];
    const float* b2          = (const float*)d_in[15];
    const int*   op_ids      = (const int*)d_in[16];
    const int*   src         = (const int*)d_in[17];
    const int*   dst         = (const int*)d_in[18];
    float* out = (float*)d_out;

    float* hp;
    __half* x16p;
    __nv_bfloat16 *Abh, *Abl, *WBh, *WBl, *W1h, *W1l, *W2h, *W2l;
    cudaGetSymbolAddress((void**)&hp, g_h);
    cudaGetSymbolAddress((void**)&x16p, g_x16);
    cudaGetSymbolAddress((void**)&Abh, g_Abh);
    cudaGetSymbolAddress((void**)&Abl, g_Abl);
    cudaGetSymbolAddress((void**)&WBh, g_WBh);
    cudaGetSymbolAddress((void**)&WBl, g_WBl);
    cudaGetSymbolAddress((void**)&W1h, g_W1h);
    cudaGetSymbolAddress((void**)&W1l, g_W1l);
    cudaGetSymbolAddress((void**)&W2h, g_W2h);
    cudaGetSymbolAddress((void**)&W2l, g_W2l);

    zero_kernel<<<(N_NODES + 255) / 256, 256>>>();
    deg_kernel<<<(N_EDGES + 255) / 256, 256>>>(dst);
    scan_kernel<<<1, 256>>>();
    fill_kernel<<<(N_EDGES + 255) / 256, 256>>>(src, dst);
    split_w_kernel<<<(W_TOT + 255) / 256, 256>>>(Wself, Wneigh, W1, W2);

    build_x_kernel<<<N_NODES, HID>>>(op_feats, config_f, embed_table,
                                     feat_mean, feat_std, op_ids);

    dim3 ggrid((N_NODES + BM - 1) / BM, HID / BN);        // 157 x 4
    dim3 ggrid2((N_NODES + BM - 1) / BM, (HID / 2) / BN); // 157 x 2

    for (int i = 0; i < 4; i++) {
        agg_kernel<<<N_NODES, 64>>>();
        gemm_bf16_kernel<<<ggrid, 256>>>(
            Abh, Abl, KB2, WBh + i * HID * KB2, WBl + i * HID * KB2, KB2,
            bconv + i * HID, hp, KB2, HID);
        ln_relu_kernel<<<N_NODES, HID>>>(hp, nullptr, Abh, Abl,
                                         (i < 3) ? x16p : (__half*)nullptr,
                                         conv_gamma + i * HID, conv_beta + i * HID, HID);
    }

    gemm_bf16_kernel<<<ggrid, 256>>>(Abh, Abl, KB2, W1h, W1l, HID,
                                     nullptr, hp, HID, HID);
    ln_relu_kernel<<<N_NODES, HID>>>(hp, nullptr, Abh, Abl, nullptr, g1, b1, HID);

    gemm_bf16_kernel<<<ggrid2, 256>>>(Abh, Abl, KB2, W2h, W2l, HID,
                                      nullptr, hp, HID, HID / 2);
    ln_relu_kernel<<<N_NODES, HID / 2>>>(hp, out, nullptr, nullptr, nullptr, g2, b2, HID / 2);
}

// round 9
// speedup vs baseline: 1.3910x; 1.0351x over previous
#include <cuda_runtime.h>
#include <cuda_fp16.h>
#include <cuda_bf16.h>
#include <cstdint>

#define N_NODES 20000
#define N_EDGES 640000
#define HID 256
#define KB2 512
#define D_OP 140
#define D_EMB 64
#define D_CFG 52
#define LN_EPS 1e-5f

// ---------------- scratch (device globals; no allocation) ----------------
__device__ __nv_bfloat16 g_Abh[N_NODES * KB2];   // A hi: cols 0-255 = x, 256-511 = agg
__device__ __nv_bfloat16 g_Abl[N_NODES * KB2];   // A lo
__device__ __half        g_x16[N_NODES * HID];   // fp16 shadow for agg gather
__device__ float         g_h[N_NODES * HID];     // GEMM output
__device__ __nv_bfloat16 g_WBh[4 * HID * KB2];   // [layer][n=256][k=512] transposed concat W
__device__ __nv_bfloat16 g_WBl[4 * HID * KB2];
__device__ __nv_bfloat16 g_W1h[HID * HID];       // [n=256][k=256]
__device__ __nv_bfloat16 g_W1l[HID * HID];
__device__ __nv_bfloat16 g_W2h[(HID / 2) * HID]; // [n=128][k=256]
__device__ __nv_bfloat16 g_W2l[(HID / 2) * HID];
__device__ int   g_deg[N_NODES];
__device__ float g_invdeg[N_NODES];
__device__ int   g_rowstart[N_NODES + 1];
__device__ int   g_cursor[N_NODES];
__device__ int   g_csr[N_EDGES];

__device__ __forceinline__ void bf16split(float v, __nv_bfloat16& h, __nv_bfloat16& l) {
    h = __float2bfloat16_rn(v);
    l = __float2bfloat16_rn(v - __bfloat162float(h));
}

// ---------------- graph preprocessing ----------------
__global__ void zero_kernel() {
    int i = blockIdx.x * blockDim.x + threadIdx.x;
    if (i < N_NODES) { g_deg[i] = 0; g_cursor[i] = 0; }
}

__global__ void deg_kernel(const int* __restrict__ dst) {
    int e = blockIdx.x * blockDim.x + threadIdx.x;
    if (e < N_EDGES) atomicAdd(&g_deg[dst[e]], 1);
}

__global__ void scan_kernel() {
    __shared__ int partial[256];
    int tid = threadIdx.x;
    const int CH = (N_NODES + 255) / 256;
    int base = tid * CH;
    int s = 0;
    for (int i = 0; i < CH; i++) {
        int idx = base + i;
        if (idx < N_NODES) s += g_deg[idx];
    }
    partial[tid] = s;
    __syncthreads();
    for (int off = 1; off < 256; off <<= 1) {
        int v = 0;
        if (tid >= off) v = partial[tid - off];
        __syncthreads();
        partial[tid] += v;
        __syncthreads();
    }
    int run = (tid == 0) ? 0 : partial[tid - 1];
    for (int i = 0; i < CH; i++) {
        int idx = base + i;
        if (idx < N_NODES) {
            int d = g_deg[idx];
            g_rowstart[idx] = run;
            run += d;
            g_invdeg[idx] = 1.0f / fmaxf((float)d, 1.0f);
        }
    }
    if (tid == 255) g_rowstart[N_NODES] = run;
}

__global__ void fill_kernel(const int* __restrict__ src, const int* __restrict__ dst) {
    int e = blockIdx.x * blockDim.x + threadIdx.x;
    if (e < N_EDGES) {
        int d = dst[e];
        int pos = atomicAdd(&g_cursor[d], 1);
        g_csr[g_rowstart[d] + pos] = src[e];
    }
}

// ---------------- weight transpose + bf16 split (once per launch) ----------------
#define W_LAYER (4 * HID * KB2)               // 524288
#define W_TOT (W_LAYER + HID * HID + (HID / 2) * HID)
__global__ void split_w_kernel(const float* __restrict__ Wself,
                               const float* __restrict__ Wneigh,
                               const float* __restrict__ W1,
                               const float* __restrict__ W2) {
    int i = blockIdx.x * blockDim.x + threadIdx.x;
    if (i >= W_TOT) return;
    float v; __nv_bfloat16* dh; __nv_bfloat16* dl; int di;
    if (i < W_LAYER) {
        int l = i >> 17;
        int rem = i & (HID * KB2 - 1);
        int n = rem >> 9, k = rem & 511;
        v = (k < HID) ? Wself[(l * HID + k) * HID + n]
                      : Wneigh[(l * HID + (k - HID)) * HID + n];
        dh = g_WBh; dl = g_WBl; di = i;
    } else if (i < W_LAYER + HID * HID) {
        di = i - W_LAYER;
        int n = di >> 8, k = di & 255;
        v = W1[k * HID + n];
        dh = g_W1h; dl = g_W1l;
    } else {
        di = i - (W_LAYER + HID * HID);
        int n = di >> 8, k = di & 255;
        v = W2[k * (HID / 2) + n];
        dh = g_W2h; dl = g_W2l;
    }
    bf16split(v, dh[di], dl[di]);
}

// ---------------- input feature assembly ----------------
__global__ void build_x_kernel(const float* __restrict__ op_feats,
                               const float* __restrict__ cfg,
                               const float* __restrict__ emb,
                               const float* __restrict__ fmean,
                               const float* __restrict__ fstd,
                               const int* __restrict__ op_ids) {
    int n = blockIdx.x;
    int c = threadIdx.x;
    float v;
    if (c < D_OP)               v = op_feats[n * D_OP + c];
    else if (c < D_OP + D_EMB)  v = emb[op_ids[n] * D_EMB + (c - D_OP)];
    else                        v = cfg[n * D_CFG + (c - D_OP - D_EMB)];
    float xv = (v - fmean[c]) / fstd[c];
    bf16split(xv, g_Abh[n * KB2 + c], g_Abl[n * KB2 + c]);
    g_x16[n * HID + c] = __float2half(xv);
}

// ---------------- neighbor mean aggregation ----------------
__global__ __launch_bounds__(64) void agg_kernel() {
    int n = blockIdx.x;
    int t = threadIdx.x;
    int s0 = g_rowstart[n], s1 = g_rowstart[n + 1];
    const uint2* __restrict__ xv = (const uint2*)g_x16;

    float4 acc = make_float4(0.f, 0.f, 0.f, 0.f);

    int j = s0;
    for (; j + 4 <= s1; j += 4) {
        int i0 = g_csr[j], i1 = g_csr[j + 1], i2 = g_csr[j + 2], i3 = g_csr[j + 3];
        uint2 r0 = xv[i0 * 64 + t];
        uint2 r1 = xv[i1 * 64 + t];
        uint2 r2 = xv[i2 * 64 + t];
        uint2 r3 = xv[i3 * 64 + t];
#pragma unroll
        for (int q = 0; q < 4; q++) {
            uint2 r = (q == 0) ? r0 : (q == 1) ? r1 : (q == 2) ? r2 : r3;
            float2 a = __half22float2(*(const __half2*)&r.x);
            float2 b = __half22float2(*(const __half2*)&r.y);
            acc.x += a.x; acc.y += a.y; acc.z += b.x; acc.w += b.y;
        }
    }
    for (; j < s1; j++) {
        uint2 r = xv[g_csr[j] * 64 + t];
        float2 a = __half22float2(*(const __half2*)&r.x);
        float2 b = __half22float2(*(const __half2*)&r.y);
        acc.x += a.x; acc.y += a.y; acc.z += b.x; acc.w += b.y;
    }
    float id = g_invdeg[n];
    float vv[4] = {acc.x * id, acc.y * id, acc.z * id, acc.w * id};
    __nv_bfloat16 hh[4], ll[4];
#pragma unroll
    for (int i = 0; i < 4; i++) bf16split(vv[i], hh[i], ll[i]);
    *(uint2*)&g_Abh[n * KB2 + HID + t * 4] = *(const uint2*)hh;
    *(uint2*)&g_Abl[n * KB2 + HID + t * 4] = *(const uint2*)ll;
}

// ---------------- bf16x3 GEMM, cp.async 2-stage double-buffered ----------------
#define BM 128
#define BN 64
#define BK 32
#define AS 40   // halves per A smem row
#define BS 40
// smem layout (halves), per stage
#define ASH_OFF 0
#define ASL_OFF (BM * AS)                 // 5120
#define BSH_OFF (2 * BM * AS)             // 10240
#define BSL_OFF (2 * BM * AS + BN * BS)   // 12800
#define STAGE_HALVES (2 * BM * AS + 2 * BN * BS)  // 15360 (30720 B)
#define GEMM_SMEM (2 * STAGE_HALVES * 2)  // 61440 B

__device__ __forceinline__ uint32_t sm_u32(const void* p) {
    uint32_t a;
    asm("{ .reg .u64 t; cvta.to.shared.u64 t, %1; cvt.u32.u64 %0, t; }" : "=r"(a) : "l"(p));
    return a;
}
__device__ __forceinline__ void cp16(uint32_t d, const void* s) {
    asm volatile("cp.async.cg.shared.global [%0], [%1], 16;" :: "r"(d), "l"(s));
}
__device__ __forceinline__ void cp16z(uint32_t d, const void* s, int sz) {
    asm volatile("cp.async.cg.shared.global [%0], [%1], 16, %2;" :: "r"(d), "l"(s), "r"(sz));
}

__device__ __forceinline__ void mma_bf16(float* c, const uint32_t* a, const uint32_t* b) {
    asm volatile(
        "mma.sync.aligned.m16n8k16.row.col.f32.bf16.bf16.f32 "
        "{%0,%1,%2,%3}, {%4,%5,%6,%7}, {%8,%9}, {%0,%1,%2,%3};"
        : "+f"(c[0]), "+f"(c[1]), "+f"(c[2]), "+f"(c[3])
        : "r"(a[0]), "r"(a[1]), "r"(a[2]), "r"(a[3]), "r"(b[0]), "r"(b[1]));
}

__global__ __launch_bounds__(256) void gemm_bf16_kernel(
    const __nv_bfloat16* __restrict__ Agh, const __nv_bfloat16* __restrict__ Agl, int lda,
    const __nv_bfloat16* __restrict__ Bgh, const __nv_bfloat16* __restrict__ Bgl, int ldb,
    const float* __restrict__ bias, float* __restrict__ C, int K, int NC)
{
    extern __shared__ uint16_t smem[];
    uint32_t s_base = sm_u32(smem);

    int tid = threadIdx.x;
    int lane = tid & 31, wid = tid >> 5;
    int warp_m = wid & 3, warp_n = wid >> 2;
    int g = lane >> 2, tig = lane & 3;

    int row0 = blockIdx.x * BM;
    int col0 = blockIdx.y * BN;

    // A: 128 rows x 4 chunks(8 halves) = 512 chunks; 2 per thread (each issues hi+lo)
    int am[2], ak[2];
#pragma unroll
    for (int r = 0; r < 2; r++) {
        int c = tid + 256 * r;      // 0..511
        am[r] = c >> 2;             // 0..127
        ak[r] = (c & 3) * 8;        // 0,8,16,24
    }
    // B: 64 rows x 4 chunks = 256 chunks; 1 per thread (issues hi+lo)
    int bn_ = tid >> 2, bk_ = (tid & 3) * 8;

    float acc[2][4][4];
#pragma unroll
    for (int mt = 0; mt < 2; mt++)
#pragma unroll
        for (int nt = 0; nt < 4; nt++)
#pragma unroll
            for (int i = 0; i < 4; i++) acc[mt][nt][i] = 0.f;

    const int NIT = K / BK;

    auto ISSUE = [&](int it, int buf) {
        int k0 = it * BK;
        uint32_t st = s_base + buf * (STAGE_HALVES * 2);
#pragma unroll
        for (int r = 0; r < 2; r++) {
            int gm = row0 + am[r];
            int cgm = (gm < N_NODES) ? gm : (N_NODES - 1);
            int sz = (gm < N_NODES) ? 16 : 0;
            size_t off = (size_t)cgm * lda + k0 + ak[r];
            uint32_t so = (am[r] * AS + ak[r]) * 2;
            cp16z(st + ASH_OFF * 2 + so, Agh + off, sz);
            cp16z(st + ASL_OFF * 2 + so, Agl + off, sz);
        }
        {
            size_t off = (size_t)(col0 + bn_) * ldb + k0 + bk_;
            uint32_t so = (bn_ * BS + bk_) * 2;
            cp16(st + BSH_OFF * 2 + so, Bgh + off);
            cp16(st + BSL_OFF * 2 + so, Bgl + off);
        }
        asm volatile("cp.async.commit_group;");
    };

    auto COMPUTE = [&](int buf) {
        const uint16_t* Ash = smem + buf * STAGE_HALVES + ASH_OFF;
        const uint16_t* Asl = smem + buf * STAGE_HALVES + ASL_OFF;
        const uint16_t* Bsh = smem + buf * STAGE_HALVES + BSH_OFF;
        const uint16_t* Bsl = smem + buf * STAGE_HALVES + BSL_OFF;
#pragma unroll
        for (int ks = 0; ks < 2; ks++) {
            int kb = ks * 16 + 2 * tig;
            uint32_t ah[2][4], al[2][4], bh[4][2], bl[4][2];
#pragma unroll
            for (int mt = 0; mt < 2; mt++) {
                int mrow = warp_m * 32 + mt * 16 + g;
                ah[mt][0] = *(const uint32_t*)&Ash[mrow * AS + kb];
                ah[mt][1] = *(const uint32_t*)&Ash[(mrow + 8) * AS + kb];
                ah[mt][2] = *(const uint32_t*)&Ash[mrow * AS + kb + 8];
                ah[mt][3] = *(const uint32_t*)&Ash[(mrow + 8) * AS + kb + 8];
                al[mt][0] = *(const uint32_t*)&Asl[mrow * AS + kb];
                al[mt][1] = *(const uint32_t*)&Asl[(mrow + 8) * AS + kb];
                al[mt][2] = *(const uint32_t*)&Asl[mrow * AS + kb + 8];
                al[mt][3] = *(const uint32_t*)&Asl[(mrow + 8) * AS + kb + 8];
            }
#pragma unroll
            for (int nt = 0; nt < 4; nt++) {
                int ncol = warp_n * 32 + nt * 8 + g;
                bh[nt][0] = *(const uint32_t*)&Bsh[ncol * BS + kb];
                bh[nt][1] = *(const uint32_t*)&Bsh[ncol * BS + kb + 8];
                bl[nt][0] = *(const uint32_t*)&Bsl[ncol * BS + kb];
                bl[nt][1] = *(const uint32_t*)&Bsl[ncol * BS + kb + 8];
            }
#pragma unroll
            for (int mt = 0; mt < 2; mt++)
#pragma unroll
                for (int nt = 0; nt < 4; nt++) {
                    mma_bf16(acc[mt][nt], ah[mt], bh[nt]);
                    mma_bf16(acc[mt][nt], al[mt], bh[nt]);
                    mma_bf16(acc[mt][nt], ah[mt], bl[nt]);
                }
        }
    };

    ISSUE(0, 0);
    int buf = 0;
    for (int it = 0; it < NIT; it++) {
        if (it + 1 < NIT) {
            ISSUE(it + 1, buf ^ 1);
            asm volatile("cp.async.wait_group 1;");
        } else {
            asm volatile("cp.async.wait_group 0;");
        }
        __syncthreads();
        COMPUTE(buf);
        __syncthreads();
        buf ^= 1;
    }

    // epilogue
#pragma unroll
    for (int nt = 0; nt < 4; nt++) {
        int gc = col0 + warp_n * 32 + nt * 8 + 2 * tig;
        float b0 = bias ? bias[gc] : 0.f;
        float b1 = bias ? bias[gc + 1] : 0.f;
#pragma unroll
        for (int mt = 0; mt < 2; mt++) {
            int gr0 = row0 + warp_m * 32 + mt * 16 + g;
            if (gr0 < N_NODES) {
                float2 o = make_float2(acc[mt][nt][0] + b0, acc[mt][nt][1] + b1);
                *(float2*)&C[gr0 * NC + gc] = o;
            }
            int gr1 = gr0 + 8;
            if (gr1 < N_NODES) {
                float2 o = make_float2(acc[mt][nt][2] + b0, acc[mt][nt][3] + b1);
                *(float2*)&C[gr1 * NC + gc] = o;
            }
        }
    }
}

// ---------------- LayerNorm + ReLU ----------------
__global__ void ln_relu_kernel(const float* __restrict__ in,
                               float* __restrict__ outF,
                               __nv_bfloat16* __restrict__ outH,
                               __nv_bfloat16* __restrict__ outL,
                               __half* __restrict__ out16,
                               const float* __restrict__ gamma, const float* __restrict__ beta,
                               int D) {
    int row = blockIdx.x;
    int t = threadIdx.x;
    float v = in[row * D + t];

    __shared__ float ws[8];
    int w = t >> 5, l = t & 31, nw = D >> 5;

    float s = v;
#pragma unroll
    for (int o = 16; o; o >>= 1) s += __shfl_xor_sync(0xFFFFFFFFu, s, o);
    if (l == 0) ws[w] = s;
    __syncthreads();
    float tot = 0.f;
    for (int i = 0; i < nw; i++) tot += ws[i];
    float mu = tot / (float)D;
    __syncthreads();

    float d = v - mu;
    float s2 = d * d;
#pragma unroll
    for (int o = 16; o; o >>= 1) s2 += __shfl_xor_sync(0xFFFFFFFFu, s2, o);
    if (l == 0) ws[w] = s2;
    __syncthreads();
    float tot2 = 0.f;
    for (int i = 0; i < nw; i++) tot2 += ws[i];
    float var = tot2 / (float)D;

    float y = fmaxf(d * rsqrtf(var + LN_EPS) * gamma[t] + beta[t], 0.f);
    if (outF) outF[row * D + t] = y;
    if (outH) bf16split(y, outH[row * KB2 + t], outL[row * KB2 + t]);
    if (out16) out16[row * D + t] = __float2half(y);
}

// ---------------- launch ----------------
extern "C" void kernel_launch(void* const* d_in, const int* in_sizes, int n_in,
                              void* d_out, int out_size) {
    const float* op_feats    = (const float*)d_in[0];
    const float* config_f    = (const float*)d_in[1];
    const float* embed_table = (const float*)d_in[2];
    const float* feat_mean   = (const float*)d_in[3];
    const float* feat_std    = (const float*)d_in[4];
    const float* Wself       = (const float*)d_in[5];
    const float* Wneigh      = (const float*)d_in[6];
    const float* bconv       = (const float*)d_in[7];
    const float* conv_gamma  = (const float*)d_in[8];
    const float* conv_beta   = (const float*)d_in[9];
    const float* W1          = (const float*)d_in[10];
    const float* g1          = (const float*)d_in[11];
    const float* b1          = (const float*)d_in[12];
    const float* W2          = (const float*)d_in[13];
    const float* g2          = (const float*)d_in[14];
    const float* b2          = (const float*)d_in[15];
    const int*   op_ids      = (const int*)d_in[16];
    const int*   src         = (const int*)d_in[17];
    const int*   dst         = (const int*)d_in[18];
    float* out = (float*)d_out;

    float* hp;
    __half* x16p;
    __nv_bfloat16 *Abh, *Abl, *WBh, *WBl, *W1h, *W1l, *W2h, *W2l;
    cudaGetSymbolAddress((void**)&hp, g_h);
    cudaGetSymbolAddress((void**)&x16p, g_x16);
    cudaGetSymbolAddress((void**)&Abh, g_Abh);
    cudaGetSymbolAddress((void**)&Abl, g_Abl);
    cudaGetSymbolAddress((void**)&WBh, g_WBh);
    cudaGetSymbolAddress((void**)&WBl, g_WBl);
    cudaGetSymbolAddress((void**)&W1h, g_W1h);
    cudaGetSymbolAddress((void**)&W1l, g_W1l);
    cudaGetSymbolAddress((void**)&W2h, g_W2h);
    cudaGetSymbolAddress((void**)&W2l, g_W2l);

    cudaFuncSetAttribute(gemm_bf16_kernel,
                         cudaFuncAttributeMaxDynamicSharedMemorySize, GEMM_SMEM);

    zero_kernel<<<(N_NODES + 255) / 256, 256>>>();
    deg_kernel<<<(N_EDGES + 255) / 256, 256>>>(dst);
    scan_kernel<<<1, 256>>>();
    fill_kernel<<<(N_EDGES + 255) / 256, 256>>>(src, dst);
    split_w_kernel<<<(W_TOT + 255) / 256, 256>>>(Wself, Wneigh, W1, W2);

    build_x_kernel<<<N_NODES, HID>>>(op_feats, config_f, embed_table,
                                     feat_mean, feat_std, op_ids);

    dim3 ggrid((N_NODES + BM - 1) / BM, HID / BN);        // 157 x 4
    dim3 ggrid2((N_NODES + BM - 1) / BM, (HID / 2) / BN); // 157 x 2

    for (int i = 0; i < 4; i++) {
        agg_kernel<<<N_NODES, 64>>>();
        gemm_bf16_kernel<<<ggrid, 256, GEMM_SMEM>>>(
            Abh, Abl, KB2, WBh + i * HID * KB2, WBl + i * HID * KB2, KB2,
            bconv + i * HID, hp, KB2, HID);
        ln_relu_kernel<<<N_NODES, HID>>>(hp, nullptr, Abh, Abl,
                                         (i < 3) ? x16p : (__half*)nullptr,
                                         conv_gamma + i * HID, conv_beta + i * HID, HID);
    }

    gemm_bf16_kernel<<<ggrid, 256, GEMM_SMEM>>>(Abh, Abl, KB2, W1h, W1l, HID,
                                                nullptr, hp, HID, HID);
    ln_relu_kernel<<<N_NODES, HID>>>(hp, nullptr, Abh, Abl, nullptr, g1, b1, HID);

    gemm_bf16_kernel<<<ggrid2, 256, GEMM_SMEM>>>(Abh, Abl, KB2, W2h, W2l, HID,
                                                 nullptr, hp, HID, HID / 2);
    ln_relu_kernel<<<N_NODES, HID / 2>>>(hp, out, nullptr, nullptr, nullptr, g2, b2, HID / 2);
}

// round 10
// speedup vs baseline: 1.4602x; 1.0497x over previous
#include <cuda_runtime.h>
#include <cuda_fp16.h>
#include <cuda_bf16.h>
#include <cstdint>

#define N_NODES 20000
#define N_EDGES 640000
#define HID 256
#define KB2 512
#define D_OP 140
#define D_EMB 64
#define D_CFG 52
#define LN_EPS 1e-5f

// ---------------- scratch (device globals; no allocation) ----------------
__device__ __nv_bfloat16 g_Abh[N_NODES * KB2];   // A hi: cols 0-255 = x, 256-511 = agg
__device__ __nv_bfloat16 g_Abl[N_NODES * KB2];   // A lo
__device__ __half        g_x16[N_NODES * HID];   // fp16 shadow for agg gather
__device__ float         g_h[N_NODES * HID];     // GEMM output
__device__ __nv_bfloat16 g_WBh[4 * HID * KB2];   // [layer][n=256][k=512] transposed concat W
__device__ __nv_bfloat16 g_WBl[4 * HID * KB2];
__device__ __nv_bfloat16 g_W1h[HID * HID];       // [n=256][k=256]
__device__ __nv_bfloat16 g_W1l[HID * HID];
__device__ __nv_bfloat16 g_W2h[(HID / 2) * HID]; // [n=128][k=256]
__device__ __nv_bfloat16 g_W2l[(HID / 2) * HID];
__device__ int   g_deg[N_NODES];
__device__ float g_invdeg[N_NODES];
__device__ int   g_rowstart[N_NODES + 1];
__device__ int   g_cursor[N_NODES];
__device__ int   g_csr[N_EDGES];

__device__ __forceinline__ void bf16split(float v, __nv_bfloat16& h, __nv_bfloat16& l) {
    h = __float2bfloat16_rn(v);
    l = __float2bfloat16_rn(v - __bfloat162float(h));
}

// ---------------- graph preprocessing ----------------
__global__ void zero_kernel() {
    int i = blockIdx.x * blockDim.x + threadIdx.x;
    if (i < N_NODES) { g_deg[i] = 0; g_cursor[i] = 0; }
}

__global__ void deg_kernel(const int* __restrict__ dst) {
    int e = blockIdx.x * blockDim.x + threadIdx.x;
    if (e < N_EDGES) atomicAdd(&g_deg[dst[e]], 1);
}

__global__ void scan_kernel() {
    __shared__ int partial[256];
    int tid = threadIdx.x;
    const int CH = (N_NODES + 255) / 256;
    int base = tid * CH;
    int s = 0;
    for (int i = 0; i < CH; i++) {
        int idx = base + i;
        if (idx < N_NODES) s += g_deg[idx];
    }
    partial[tid] = s;
    __syncthreads();
    for (int off = 1; off < 256; off <<= 1) {
        int v = 0;
        if (tid >= off) v = partial[tid - off];
        __syncthreads();
        partial[tid] += v;
        __syncthreads();
    }
    int run = (tid == 0) ? 0 : partial[tid - 1];
    for (int i = 0; i < CH; i++) {
        int idx = base + i;
        if (idx < N_NODES) {
            int d = g_deg[idx];
            g_rowstart[idx] = run;
            run += d;
            g_invdeg[idx] = 1.0f / fmaxf((float)d, 1.0f);
        }
    }
    if (tid == 255) g_rowstart[N_NODES] = run;
}

__global__ void fill_kernel(const int* __restrict__ src, const int* __restrict__ dst) {
    int e = blockIdx.x * blockDim.x + threadIdx.x;
    if (e < N_EDGES) {
        int d = dst[e];
        int pos = atomicAdd(&g_cursor[d], 1);
        g_csr[g_rowstart[d] + pos] = src[e];
    }
}

// ---------------- weight transpose + bf16 split (once per launch) ----------------
#define W_LAYER (4 * HID * KB2)               // 524288
#define W_TOT (W_LAYER + HID * HID + (HID / 2) * HID)
__global__ void split_w_kernel(const float* __restrict__ Wself,
                               const float* __restrict__ Wneigh,
                               const float* __restrict__ W1,
                               const float* __restrict__ W2) {
    int i = blockIdx.x * blockDim.x + threadIdx.x;
    if (i >= W_TOT) return;
    float v; __nv_bfloat16* dh; __nv_bfloat16* dl; int di;
    if (i < W_LAYER) {
        int l = i >> 17;
        int rem = i & (HID * KB2 - 1);
        int n = rem >> 9, k = rem & 511;
        v = (k < HID) ? Wself[(l * HID + k) * HID + n]
                      : Wneigh[(l * HID + (k - HID)) * HID + n];
        dh = g_WBh; dl = g_WBl; di = i;
    } else if (i < W_LAYER + HID * HID) {
        di = i - W_LAYER;
        int n = di >> 8, k = di & 255;
        v = W1[k * HID + n];
        dh = g_W1h; dl = g_W1l;
    } else {
        di = i - (W_LAYER + HID * HID);
        int n = di >> 8, k = di & 255;
        v = W2[k * (HID / 2) + n];
        dh = g_W2h; dl = g_W2l;
    }
    bf16split(v, dh[di], dl[di]);
}

// ---------------- input feature assembly ----------------
__global__ void build_x_kernel(const float* __restrict__ op_feats,
                               const float* __restrict__ cfg,
                               const float* __restrict__ emb,
                               const float* __restrict__ fmean,
                               const float* __restrict__ fstd,
                               const int* __restrict__ op_ids) {
    int n = blockIdx.x;
    int c = threadIdx.x;
    float v;
    if (c < D_OP)               v = op_feats[n * D_OP + c];
    else if (c < D_OP + D_EMB)  v = emb[op_ids[n] * D_EMB + (c - D_OP)];
    else                        v = cfg[n * D_CFG + (c - D_OP - D_EMB)];
    float xv = (v - fmean[c]) / fstd[c];
    bf16split(xv, g_Abh[n * KB2 + c], g_Abl[n * KB2 + c]);
    g_x16[n * HID + c] = __float2half(xv);
}

// ---------------- neighbor mean aggregation ----------------
__global__ __launch_bounds__(64) void agg_kernel() {
    int n = blockIdx.x;
    int t = threadIdx.x;
    int s0 = g_rowstart[n], s1 = g_rowstart[n + 1];
    const uint2* __restrict__ xv = (const uint2*)g_x16;

    float4 acc = make_float4(0.f, 0.f, 0.f, 0.f);

    int j = s0;
    for (; j + 4 <= s1; j += 4) {
        int i0 = g_csr[j], i1 = g_csr[j + 1], i2 = g_csr[j + 2], i3 = g_csr[j + 3];
        uint2 r0 = xv[i0 * 64 + t];
        uint2 r1 = xv[i1 * 64 + t];
        uint2 r2 = xv[i2 * 64 + t];
        uint2 r3 = xv[i3 * 64 + t];
#pragma unroll
        for (int q = 0; q < 4; q++) {
            uint2 r = (q == 0) ? r0 : (q == 1) ? r1 : (q == 2) ? r2 : r3;
            float2 a = __half22float2(*(const __half2*)&r.x);
            float2 b = __half22float2(*(const __half2*)&r.y);
            acc.x += a.x; acc.y += a.y; acc.z += b.x; acc.w += b.y;
        }
    }
    for (; j < s1; j++) {
        uint2 r = xv[g_csr[j] * 64 + t];
        float2 a = __half22float2(*(const __half2*)&r.x);
        float2 b = __half22float2(*(const __half2*)&r.y);
        acc.x += a.x; acc.y += a.y; acc.z += b.x; acc.w += b.y;
    }
    float id = g_invdeg[n];
    float vv[4] = {acc.x * id, acc.y * id, acc.z * id, acc.w * id};
    __nv_bfloat16 hh[4], ll[4];
#pragma unroll
    for (int i = 0; i < 4; i++) bf16split(vv[i], hh[i], ll[i]);
    *(uint2*)&g_Abh[n * KB2 + HID + t * 4] = *(const uint2*)hh;
    *(uint2*)&g_Abl[n * KB2 + HID + t * 4] = *(const uint2*)ll;
}

// ---------------- bf16x3 GEMM, cp.async double-buffered + ldmatrix ----------------
#define BM 128
#define BN 64
#define BK 32
#define AS 40   // halves per A smem row (80B, 16B-aligned, LDSM conflict-free)
#define BS 40
// smem layout (halves), per stage
#define ASH_OFF 0
#define ASL_OFF (BM * AS)                 // 5120
#define BSH_OFF (2 * BM * AS)             // 10240
#define BSL_OFF (2 * BM * AS + BN * BS)   // 12800
#define STAGE_HALVES (2 * BM * AS + 2 * BN * BS)  // 15360 (30720 B)
#define GEMM_SMEM (2 * STAGE_HALVES * 2)  // 61440 B

__device__ __forceinline__ uint32_t sm_u32(const void* p) {
    uint32_t a;
    asm("{ .reg .u64 t; cvta.to.shared.u64 t, %1; cvt.u32.u64 %0, t; }" : "=r"(a) : "l"(p));
    return a;
}
__device__ __forceinline__ void cp16(uint32_t d, const void* s) {
    asm volatile("cp.async.cg.shared.global [%0], [%1], 16;" :: "r"(d), "l"(s));
}
__device__ __forceinline__ void cp16z(uint32_t d, const void* s, int sz) {
    asm volatile("cp.async.cg.shared.global [%0], [%1], 16, %2;" :: "r"(d), "l"(s), "r"(sz));
}
__device__ __forceinline__ void ldsm4(uint32_t* r, uint32_t addr) {
    asm volatile("ldmatrix.sync.aligned.m8n8.x4.shared.b16 {%0,%1,%2,%3}, [%4];"
        : "=r"(r[0]), "=r"(r[1]), "=r"(r[2]), "=r"(r[3]) : "r"(addr));
}

__device__ __forceinline__ void mma_bf16(float* c, const uint32_t* a, const uint32_t* b) {
    asm volatile(
        "mma.sync.aligned.m16n8k16.row.col.f32.bf16.bf16.f32 "
        "{%0,%1,%2,%3}, {%4,%5,%6,%7}, {%8,%9}, {%0,%1,%2,%3};"
        : "+f"(c[0]), "+f"(c[1]), "+f"(c[2]), "+f"(c[3])
        : "r"(a[0]), "r"(a[1]), "r"(a[2]), "r"(a[3]), "r"(b[0]), "r"(b[1]));
}

__global__ __launch_bounds__(256) void gemm_bf16_kernel(
    const __nv_bfloat16* __restrict__ Agh, const __nv_bfloat16* __restrict__ Agl, int lda,
    const __nv_bfloat16* __restrict__ Bgh, const __nv_bfloat16* __restrict__ Bgl, int ldb,
    const float* __restrict__ bias, float* __restrict__ C, int K, int NC)
{
    extern __shared__ uint16_t smem[];
    uint32_t s_base = sm_u32(smem);

    int tid = threadIdx.x;
    int lane = tid & 31, wid = tid >> 5;
    int warp_m = wid & 3, warp_n = wid >> 2;
    int g = lane >> 2, tig = lane & 3;
    int lt = lane >> 3, lr = lane & 7;       // ldmatrix tile index / row-in-tile

    int row0 = blockIdx.x * BM;
    int col0 = blockIdx.y * BN;

    // A copy map: 512 chunks of 8 halves; 2 per thread (each issues hi+lo)
    int am[2], ak[2];
#pragma unroll
    for (int r = 0; r < 2; r++) {
        int c = tid + 256 * r;
        am[r] = c >> 2;
        ak[r] = (c & 3) * 8;
    }
    // B copy map: 256 chunks; 1 per thread
    int bn_ = tid >> 2, bk_ = (tid & 3) * 8;

    float acc[2][4][4];
#pragma unroll
    for (int mt = 0; mt < 2; mt++)
#pragma unroll
        for (int nt = 0; nt < 4; nt++)
#pragma unroll
            for (int i = 0; i < 4; i++) acc[mt][nt][i] = 0.f;

    const int NIT = K / BK;

    auto ISSUE = [&](int it, int buf) {
        int k0 = it * BK;
        uint32_t st = s_base + buf * (STAGE_HALVES * 2);
#pragma unroll
        for (int r = 0; r < 2; r++) {
            int gm = row0 + am[r];
            int cgm = (gm < N_NODES) ? gm : (N_NODES - 1);
            int sz = (gm < N_NODES) ? 16 : 0;
            size_t off = (size_t)cgm * lda + k0 + ak[r];
            uint32_t so = (am[r] * AS + ak[r]) * 2;
            cp16z(st + ASH_OFF * 2 + so, Agh + off, sz);
            cp16z(st + ASL_OFF * 2 + so, Agl + off, sz);
        }
        {
            size_t off = (size_t)(col0 + bn_) * ldb + k0 + bk_;
            uint32_t so = (bn_ * BS + bk_) * 2;
            cp16(st + BSH_OFF * 2 + so, Bgh + off);
            cp16(st + BSL_OFF * 2 + so, Bgl + off);
        }
        asm volatile("cp.async.commit_group;");
    };

    auto COMPUTE = [&](int buf) {
        uint32_t st = s_base + buf * (STAGE_HALVES * 2);
#pragma unroll
        for (int ks = 0; ks < 2; ks++) {
            int k0 = ks * 16;
            uint32_t ah[2][4], al[2][4], bh[4][2], bl[4][2];
            // A fragments: one ldmatrix.x4 per (mt, array)
#pragma unroll
            for (int mt = 0; mt < 2; mt++) {
                int row = warp_m * 32 + mt * 16 + (lt & 1) * 8 + lr;
                int col = k0 + (lt >> 1) * 8;
                uint32_t off = (uint32_t)(row * AS + col) * 2;
                ldsm4(ah[mt], st + ASH_OFF * 2 + off);
                ldsm4(al[mt], st + ASL_OFF * 2 + off);
            }
            // B fragments: one ldmatrix.x4 covers two n8 fragments
#pragma unroll
            for (int p = 0; p < 2; p++) {
                int nr = warp_n * 32 + p * 16 + (lt >> 1) * 8 + lr;
                int col = k0 + (lt & 1) * 8;
                uint32_t off = (uint32_t)(nr * BS + col) * 2;
                uint32_t t[4];
                ldsm4(t, st + BSH_OFF * 2 + off);
                bh[2 * p][0] = t[0]; bh[2 * p][1] = t[1];
                bh[2 * p + 1][0] = t[2]; bh[2 * p + 1][1] = t[3];
                ldsm4(t, st + BSL_OFF * 2 + off);
                bl[2 * p][0] = t[0]; bl[2 * p][1] = t[1];
                bl[2 * p + 1][0] = t[2]; bl[2 * p + 1][1] = t[3];
            }
#pragma unroll
            for (int mt = 0; mt < 2; mt++)
#pragma unroll
                for (int nt = 0; nt < 4; nt++) {
                    mma_bf16(acc[mt][nt], ah[mt], bh[nt]);
                    mma_bf16(acc[mt][nt], al[mt], bh[nt]);
                    mma_bf16(acc[mt][nt], ah[mt], bl[nt]);
                }
        }
    };

    ISSUE(0, 0);
    int buf = 0;
    for (int it = 0; it < NIT; it++) {
        if (it + 1 < NIT) {
            ISSUE(it + 1, buf ^ 1);
            asm volatile("cp.async.wait_group 1;");
        } else {
            asm volatile("cp.async.wait_group 0;");
        }
        __syncthreads();
        COMPUTE(buf);
        __syncthreads();
        buf ^= 1;
    }

    // epilogue
#pragma unroll
    for (int nt = 0; nt < 4; nt++) {
        int gc = col0 + warp_n * 32 + nt * 8 + 2 * tig;
        float b0 = bias ? bias[gc] : 0.f;
        float b1 = bias ? bias[gc + 1] : 0.f;
#pragma unroll
        for (int mt = 0; mt < 2; mt++) {
            int gr0 = row0 + warp_m * 32 + mt * 16 + g;
            if (gr0 < N_NODES) {
                float2 o = make_float2(acc[mt][nt][0] + b0, acc[mt][nt][1] + b1);
                *(float2*)&C[gr0 * NC + gc] = o;
            }
            int gr1 = gr0 + 8;
            if (gr1 < N_NODES) {
                float2 o = make_float2(acc[mt][nt][2] + b0, acc[mt][nt][3] + b1);
                *(float2*)&C[gr1 * NC + gc] = o;
            }
        }
    }
}

// ---------------- LayerNorm + ReLU ----------------
__global__ void ln_relu_kernel(const float* __restrict__ in,
                               float* __restrict__ outF,
                               __nv_bfloat16* __restrict__ outH,
                               __nv_bfloat16* __restrict__ outL,
                               __half* __restrict__ out16,
                               const float* __restrict__ gamma, const float* __restrict__ beta,
                               int D) {
    int row = blockIdx.x;
    int t = threadIdx.x;
    float v = in[row * D + t];

    __shared__ float ws[8];
    int w = t >> 5, l = t & 31, nw = D >> 5;

    float s = v;
#pragma unroll
    for (int o = 16; o; o >>= 1) s += __shfl_xor_sync(0xFFFFFFFFu, s, o);
    if (l == 0) ws[w] = s;
    __syncthreads();
    float tot = 0.f;
    for (int i = 0; i < nw; i++) tot += ws[i];
    float mu = tot / (float)D;
    __syncthreads();

    float d = v - mu;
    float s2 = d * d;
#pragma unroll
    for (int o = 16; o; o >>= 1) s2 += __shfl_xor_sync(0xFFFFFFFFu, s2, o);
    if (l == 0) ws[w] = s2;
    __syncthreads();
    float tot2 = 0.f;
    for (int i = 0; i < nw; i++) tot2 += ws[i];
    float var = tot2 / (float)D;

    float y = fmaxf(d * rsqrtf(var + LN_EPS) * gamma[t] + beta[t], 0.f);
    if (outF) outF[row * D + t] = y;
    if (outH) bf16split(y, outH[row * KB2 + t], outL[row * KB2 + t]);
    if (out16) out16[row * D + t] = __float2half(y);
}

// ---------------- launch ----------------
extern "C" void kernel_launch(void* const* d_in, const int* in_sizes, int n_in,
                              void* d_out, int out_size) {
    const float* op_feats    = (const float*)d_in[0];
    const float* config_f    = (const float*)d_in[1];
    const float* embed_table = (const float*)d_in[2];
    const float* feat_mean   = (const float*)d_in[3];
    const float* feat_std    = (const float*)d_in[4];
    const float* Wself       = (const float*)d_in[5];
    const float* Wneigh      = (const float*)d_in[6];
    const float* bconv       = (const float*)d_in[7];
    const float* conv_gamma  = (const float*)d_in[8];
    const float* conv_beta   = (const float*)d_in[9];
    const float* W1          = (const float*)d_in[10];
    const float* g1          = (const float*)d_in[11];
    const float* b1          = (const float*)d_in[12];
    const float* W2          = (const float*)d_in[13];
    const float* g2          = (const float*)d_in[14];
    const float* b2          = (const float*)d_in[15];
    const int*   op_ids      = (const int*)d_in[16];
    const int*   src         = (const int*)d_in[17];
    const int*   dst         = (const int*)d_in[18];
    float* out = (float*)d_out;

    float* hp;
    __half* x16p;
    __nv_bfloat16 *Abh, *Abl, *WBh, *WBl, *W1h, *W1l, *W2h, *W2l;
    cudaGetSymbolAddress((void**)&hp, g_h);
    cudaGetSymbolAddress((void**)&x16p, g_x16);
    cudaGetSymbolAddress((void**)&Abh, g_Abh);
    cudaGetSymbolAddress((void**)&Abl, g_Abl);
    cudaGetSymbolAddress((void**)&WBh, g_WBh);
    cudaGetSymbolAddress((void**)&WBl, g_WBl);
    cudaGetSymbolAddress((void**)&W1h, g_W1h);
    cudaGetSymbolAddress((void**)&W1l, g_W1l);
    cudaGetSymbolAddress((void**)&W2h, g_W2h);
    cudaGetSymbolAddress((void**)&W2l, g_W2l);

    cudaFuncSetAttribute(gemm_bf16_kernel,
                         cudaFuncAttributeMaxDynamicSharedMemorySize, GEMM_SMEM);

    zero_kernel<<<(N_NODES + 255) / 256, 256>>>();
    deg_kernel<<<(N_EDGES + 255) / 256, 256>>>(dst);
    scan_kernel<<<1, 256>>>();
    fill_kernel<<<(N_EDGES + 255) / 256, 256>>>(src, dst);
    split_w_kernel<<<(W_TOT + 255) / 256, 256>>>(Wself, Wneigh, W1, W2);

    build_x_kernel<<<N_NODES, HID>>>(op_feats, config_f, embed_table,
                                     feat_mean, feat_std, op_ids);

    dim3 ggrid((N_NODES + BM - 1) / BM, HID / BN);        // 157 x 4
    dim3 ggrid2((N_NODES + BM - 1) / BM, (HID / 2) / BN); // 157 x 2

    for (int i = 0; i < 4; i++) {
        agg_kernel<<<N_NODES, 64>>>();
        gemm_bf16_kernel<<<ggrid, 256, GEMM_SMEM>>>(
            Abh, Abl, KB2, WBh + i * HID * KB2, WBl + i * HID * KB2, KB2,
            bconv + i * HID, hp, KB2, HID);
        ln_relu_kernel<<<N_NODES, HID>>>(hp, nullptr, Abh, Abl,
                                         (i < 3) ? x16p : (__half*)nullptr,
                                         conv_gamma + i * HID, conv_beta + i * HID, HID);
    }

    gemm_bf16_kernel<<<ggrid, 256, GEMM_SMEM>>>(Abh, Abl, KB2, W1h, W1l, HID,
                                                nullptr, hp, HID, HID);
    ln_relu_kernel<<<N_NODES, HID>>>(hp, nullptr, Abh, Abl, nullptr, g1, b1, HID);

    gemm_bf16_kernel<<<ggrid2, 256, GEMM_SMEM>>>(Abh, Abl, KB2, W2h, W2l, HID,
                                                 nullptr, hp, HID, HID / 2);
    ln_relu_kernel<<<N_NODES, HID / 2>>>(hp, out, nullptr, nullptr, nullptr, g2, b2, HID / 2);
}

// round 11
// speedup vs baseline: 1.6196x; 1.1092x over previous
#include <cuda_runtime.h>
#include <cuda_fp16.h>
#include <cuda_bf16.h>
#include <cstdint>

#define N_NODES 20000
#define N_EDGES 640000
#define HID 256
#define KB2 512
#define D_OP 140
#define D_EMB 64
#define D_CFG 52
#define LN_EPS 1e-5f

// ---------------- scratch (device globals; no allocation) ----------------
__device__ __nv_bfloat16 g_Abh[N_NODES * KB2];   // A hi: cols 0-255 = x, 256-511 = agg
__device__ __nv_bfloat16 g_Abl[N_NODES * KB2];   // A lo
__device__ __half        g_x16[N_NODES * HID];   // fp16 shadow for agg gather
__device__ __nv_bfloat16 g_WBh[4 * HID * KB2];   // [layer][n=256][k=512] transposed concat W
__device__ __nv_bfloat16 g_WBl[4 * HID * KB2];
__device__ __nv_bfloat16 g_W1h[HID * HID];       // [n=256][k=256]
__device__ __nv_bfloat16 g_W1l[HID * HID];
__device__ __nv_bfloat16 g_W2h[(HID / 2) * HID]; // [n=128][k=256]
__device__ __nv_bfloat16 g_W2l[(HID / 2) * HID];
__device__ int   g_deg[N_NODES];
__device__ float g_invdeg[N_NODES];
__device__ int   g_rowstart[N_NODES + 1];
__device__ int   g_cursor[N_NODES];
__device__ int   g_csr[N_EDGES];

__device__ __forceinline__ void bf16split(float v, __nv_bfloat16& h, __nv_bfloat16& l) {
    h = __float2bfloat16_rn(v);
    l = __float2bfloat16_rn(v - __bfloat162float(h));
}

// ---------------- graph preprocessing ----------------
__global__ void zero_kernel() {
    int i = blockIdx.x * blockDim.x + threadIdx.x;
    if (i < N_NODES) { g_deg[i] = 0; g_cursor[i] = 0; }
}

__global__ void deg_kernel(const int* __restrict__ dst) {
    int e = blockIdx.x * blockDim.x + threadIdx.x;
    if (e < N_EDGES) atomicAdd(&g_deg[dst[e]], 1);
}

__global__ void scan_kernel() {
    __shared__ int partial[256];
    int tid = threadIdx.x;
    const int CH = (N_NODES + 255) / 256;
    int base = tid * CH;
    int s = 0;
    for (int i = 0; i < CH; i++) {
        int idx = base + i;
        if (idx < N_NODES) s += g_deg[idx];
    }
    partial[tid] = s;
    __syncthreads();
    for (int off = 1; off < 256; off <<= 1) {
        int v = 0;
        if (tid >= off) v = partial[tid - off];
        __syncthreads();
        partial[tid] += v;
        __syncthreads();
    }
    int run = (tid == 0) ? 0 : partial[tid - 1];
    for (int i = 0; i < CH; i++) {
        int idx = base + i;
        if (idx < N_NODES) {
            int d = g_deg[idx];
            g_rowstart[idx] = run;
            run += d;
            g_invdeg[idx] = 1.0f / fmaxf((float)d, 1.0f);
        }
    }
    if (tid == 255) g_rowstart[N_NODES] = run;
}

__global__ void fill_kernel(const int* __restrict__ src, const int* __restrict__ dst) {
    int e = blockIdx.x * blockDim.x + threadIdx.x;
    if (e < N_EDGES) {
        int d = dst[e];
        int pos = atomicAdd(&g_cursor[d], 1);
        g_csr[g_rowstart[d] + pos] = src[e];
    }
}

// ---------------- weight transpose + bf16 split (once per launch) ----------------
#define W_LAYER (4 * HID * KB2)               // 524288
#define W_TOT (W_LAYER + HID * HID + (HID / 2) * HID)
__global__ void split_w_kernel(const float* __restrict__ Wself,
                               const float* __restrict__ Wneigh,
                               const float* __restrict__ W1,
                               const float* __restrict__ W2) {
    int i = blockIdx.x * blockDim.x + threadIdx.x;
    if (i >= W_TOT) return;
    float v; __nv_bfloat16* dh; __nv_bfloat16* dl; int di;
    if (i < W_LAYER) {
        int l = i >> 17;
        int rem = i & (HID * KB2 - 1);
        int n = rem >> 9, k = rem & 511;
        v = (k < HID) ? Wself[(l * HID + k) * HID + n]
                      : Wneigh[(l * HID + (k - HID)) * HID + n];
        dh = g_WBh; dl = g_WBl; di = i;
    } else if (i < W_LAYER + HID * HID) {
        di = i - W_LAYER;
        int n = di >> 8, k = di & 255;
        v = W1[k * HID + n];
        dh = g_W1h; dl = g_W1l;
    } else {
        di = i - (W_LAYER + HID * HID);
        int n = di >> 8, k = di & 255;
        v = W2[k * (HID / 2) + n];
        dh = g_W2h; dl = g_W2l;
    }
    bf16split(v, dh[di], dl[di]);
}

// ---------------- input feature assembly ----------------
__global__ void build_x_kernel(const float* __restrict__ op_feats,
                               const float* __restrict__ cfg,
                               const float* __restrict__ emb,
                               const float* __restrict__ fmean,
                               const float* __restrict__ fstd,
                               const int* __restrict__ op_ids) {
    int n = blockIdx.x;
    int c = threadIdx.x;
    float v;
    if (c < D_OP)               v = op_feats[n * D_OP + c];
    else if (c < D_OP + D_EMB)  v = emb[op_ids[n] * D_EMB + (c - D_OP)];
    else                        v = cfg[n * D_CFG + (c - D_OP - D_EMB)];
    float xv = (v - fmean[c]) / fstd[c];
    bf16split(xv, g_Abh[n * KB2 + c], g_Abl[n * KB2 + c]);
    g_x16[n * HID + c] = __float2half(xv);
}

// ---------------- neighbor mean aggregation ----------------
__global__ __launch_bounds__(64) void agg_kernel() {
    int n = blockIdx.x;
    int t = threadIdx.x;
    int s0 = g_rowstart[n], s1 = g_rowstart[n + 1];
    const uint2* __restrict__ xv = (const uint2*)g_x16;

    float4 acc = make_float4(0.f, 0.f, 0.f, 0.f);

    int j = s0;
    for (; j + 4 <= s1; j += 4) {
        int i0 = g_csr[j], i1 = g_csr[j + 1], i2 = g_csr[j + 2], i3 = g_csr[j + 3];
        uint2 r0 = xv[i0 * 64 + t];
        uint2 r1 = xv[i1 * 64 + t];
        uint2 r2 = xv[i2 * 64 + t];
        uint2 r3 = xv[i3 * 64 + t];
#pragma unroll
        for (int q = 0; q < 4; q++) {
            uint2 r = (q == 0) ? r0 : (q == 1) ? r1 : (q == 2) ? r2 : r3;
            float2 a = __half22float2(*(const __half2*)&r.x);
            float2 b = __half22float2(*(const __half2*)&r.y);
            acc.x += a.x; acc.y += a.y; acc.z += b.x; acc.w += b.y;
        }
    }
    for (; j < s1; j++) {
        uint2 r = xv[g_csr[j] * 64 + t];
        float2 a = __half22float2(*(const __half2*)&r.x);
        float2 b = __half22float2(*(const __half2*)&r.y);
        acc.x += a.x; acc.y += a.y; acc.z += b.x; acc.w += b.y;
    }
    float id = g_invdeg[n];
    float vv[4] = {acc.x * id, acc.y * id, acc.z * id, acc.w * id};
    __nv_bfloat16 hh[4], ll[4];
#pragma unroll
    for (int i = 0; i < 4; i++) bf16split(vv[i], hh[i], ll[i]);
    *(uint2*)&g_Abh[n * KB2 + HID + t * 4] = *(const uint2*)hh;
    *(uint2*)&g_Abl[n * KB2 + HID + t * 4] = *(const uint2*)ll;
}

// ---------------- fused bf16x3 GEMM + LayerNorm + ReLU ----------------
// One CTA computes FULL rows: BM=64 rows x NC cols. 8 warps = 2m x 4n.
#define BM 64
#define AS 40   // halves per smem row (80B, LDSM conflict-free)

__device__ __forceinline__ uint32_t sm_u32(const void* p) {
    uint32_t a;
    asm("{ .reg .u64 t; cvta.to.shared.u64 t, %1; cvt.u32.u64 %0, t; }" : "=r"(a) : "l"(p));
    return a;
}
__device__ __forceinline__ void cp16(uint32_t d, const void* s) {
    asm volatile("cp.async.cg.shared.global [%0], [%1], 16;" :: "r"(d), "l"(s));
}
__device__ __forceinline__ void cp16z(uint32_t d, const void* s, int sz) {
    asm volatile("cp.async.cg.shared.global [%0], [%1], 16, %2;" :: "r"(d), "l"(s), "r"(sz));
}
__device__ __forceinline__ void ldsm4(uint32_t* r, uint32_t addr) {
    asm volatile("ldmatrix.sync.aligned.m8n8.x4.shared.b16 {%0,%1,%2,%3}, [%4];"
        : "=r"(r[0]), "=r"(r[1]), "=r"(r[2]), "=r"(r[3]) : "r"(addr));
}
__device__ __forceinline__ void mma_bf16(float* c, const uint32_t* a, const uint32_t* b) {
    asm volatile(
        "mma.sync.aligned.m16n8k16.row.col.f32.bf16.bf16.f32 "
        "{%0,%1,%2,%3}, {%4,%5,%6,%7}, {%8,%9}, {%0,%1,%2,%3};"
        : "+f"(c[0]), "+f"(c[1]), "+f"(c[2]), "+f"(c[3])
        : "r"(a[0]), "r"(a[1]), "r"(a[2]), "r"(a[3]), "r"(b[0]), "r"(b[1]));
}

template <int NC>
__global__ __launch_bounds__(256) void gemm_ln_kernel(
    const __nv_bfloat16* __restrict__ Agh, const __nv_bfloat16* __restrict__ Agl, int lda,
    const __nv_bfloat16* __restrict__ Bgh, const __nv_bfloat16* __restrict__ Bgl,
    const float* __restrict__ bias,
    const float* __restrict__ gamma, const float* __restrict__ beta,
    float* __restrict__ outF,                 // stride NC (may be null)
    __nv_bfloat16* __restrict__ outH,         // stride KB2 (may be null)
    __nv_bfloat16* __restrict__ outL,
    __half* __restrict__ out16,               // stride HID (may be null)
    int K)
{
    constexpr int NT = NC / 32;               // n8-fragment count per warp
    constexpr int ASH = 0;
    constexpr int ASL = BM * AS;              // 2560
    constexpr int BSH = 2 * BM * AS;          // 5120
    constexpr int BSL = 2 * BM * AS + NC * AS;
    constexpr int STAGE = 2 * BM * AS + 2 * NC * AS;   // halves
    constexpr int NB = NC / 64;               // B chunks per thread per array

    extern __shared__ uint16_t smem[];
    __shared__ float sm_red[4][BM];
    uint32_t s_base = sm_u32(smem);

    int tid = threadIdx.x;
    int lane = tid & 31, wid = tid >> 5;
    int warp_m = wid & 1, warp_n = wid >> 1;  // 2m x 4n
    int g = lane >> 2, tig = lane & 3;
    int lt = lane >> 3, lr = lane & 7;

    int row0 = blockIdx.x * BM;

    // A copy map: 64 rows x 4 chunks = 256 chunks; 1 per thread (hi+lo)
    int am = tid >> 2, ak = (tid & 3) * 8;
    // B copy map: NC rows x 4 chunks; NB per thread (hi+lo each)
    int bn_[NB], bk_[NB];
#pragma unroll
    for (int r = 0; r < NB; r++) {
        int c = tid + 256 * r;
        bn_[r] = c >> 2;
        bk_[r] = (c & 3) * 8;
    }

    float acc[2][NT][4];
#pragma unroll
    for (int mt = 0; mt < 2; mt++)
#pragma unroll
        for (int nt = 0; nt < NT; nt++)
#pragma unroll
            for (int i = 0; i < 4; i++) acc[mt][nt][i] = 0.f;

    const int NIT = K / 32;

    auto ISSUE = [&](int it, int buf) {
        int k0 = it * 32;
        uint32_t st = s_base + buf * (STAGE * 2);
        {
            int gm = row0 + am;
            int cgm = (gm < N_NODES) ? gm : (N_NODES - 1);
            int sz = (gm < N_NODES) ? 16 : 0;
            size_t off = (size_t)cgm * lda + k0 + ak;
            uint32_t so = (am * AS + ak) * 2;
            cp16z(st + ASH * 2 + so, Agh + off, sz);
            cp16z(st + ASL * 2 + so, Agl + off, sz);
        }
#pragma unroll
        for (int r = 0; r < NB; r++) {
            size_t off = (size_t)bn_[r] * K + k0 + bk_[r];
            uint32_t so = (bn_[r] * AS + bk_[r]) * 2;
            cp16(st + BSH * 2 + so, Bgh + off);
            cp16(st + BSL * 2 + so, Bgl + off);
        }
        asm volatile("cp.async.commit_group;");
    };

    auto COMPUTE = [&](int buf) {
        uint32_t st = s_base + buf * (STAGE * 2);
#pragma unroll
        for (int ks = 0; ks < 2; ks++) {
            int k0 = ks * 16;
            uint32_t ah[2][4], al[2][4], bh[NT][2], bl[NT][2];
#pragma unroll
            for (int mt = 0; mt < 2; mt++) {
                int row = warp_m * 32 + mt * 16 + (lt & 1) * 8 + lr;
                int col = k0 + (lt >> 1) * 8;
                uint32_t off = (uint32_t)(row * AS + col) * 2;
                ldsm4(ah[mt], st + ASH * 2 + off);
                ldsm4(al[mt], st + ASL * 2 + off);
            }
#pragma unroll
            for (int p = 0; p < NT / 2; p++) {
                int nr = warp_n * (NC / 4) + p * 16 + (lt >> 1) * 8 + lr;
                int col = k0 + (lt & 1) * 8;
                uint32_t off = (uint32_t)(nr * AS + col) * 2;
                uint32_t t[4];
                ldsm4(t, st + BSH * 2 + off);
                bh[2 * p][0] = t[0]; bh[2 * p][1] = t[1];
                bh[2 * p + 1][0] = t[2]; bh[2 * p + 1][1] = t[3];
                ldsm4(t, st + BSL * 2 + off);
                bl[2 * p][0] = t[0]; bl[2 * p][1] = t[1];
                bl[2 * p + 1][0] = t[2]; bl[2 * p + 1][1] = t[3];
            }
#pragma unroll
            for (int mt = 0; mt < 2; mt++)
#pragma unroll
                for (int nt = 0; nt < NT; nt++) {
                    mma_bf16(acc[mt][nt], ah[mt], bh[nt]);
                    mma_bf16(acc[mt][nt], al[mt], bh[nt]);
                    mma_bf16(acc[mt][nt], ah[mt], bl[nt]);
                }
        }
    };

    ISSUE(0, 0);
    int buf = 0;
    for (int it = 0; it < NIT; it++) {
        if (it + 1 < NIT) {
            ISSUE(it + 1, buf ^ 1);
            asm volatile("cp.async.wait_group 1;");
        } else {
            asm volatile("cp.async.wait_group 0;");
        }
        __syncthreads();
        COMPUTE(buf);
        __syncthreads();
        buf ^= 1;
    }

    // ---------------- fused epilogue: bias + LayerNorm + ReLU + writes ----------------
    // add bias in place
#pragma unroll
    for (int nt = 0; nt < NT; nt++) {
        int gc = warp_n * (NC / 4) + nt * 8 + 2 * tig;
        float b0 = bias ? bias[gc] : 0.f;
        float b1 = bias ? bias[gc + 1] : 0.f;
#pragma unroll
        for (int mt = 0; mt < 2; mt++) {
            acc[mt][nt][0] += b0; acc[mt][nt][1] += b1;
            acc[mt][nt][2] += b0; acc[mt][nt][3] += b1;
        }
    }

    // pass 1: row sums -> mean  (rows r0 = warp_m*32+mt*16+g, r1 = r0+8)
    float mu[2][2];
#pragma unroll
    for (int mt = 0; mt < 2; mt++) {
        float s0 = 0.f, s1 = 0.f;
#pragma unroll
        for (int nt = 0; nt < NT; nt++) {
            s0 += acc[mt][nt][0] + acc[mt][nt][1];
            s1 += acc[mt][nt][2] + acc[mt][nt][3];
        }
        // combine across tig (lanes differ in bits 0-1)
        s0 += __shfl_xor_sync(0xFFFFFFFFu, s0, 1);
        s0 += __shfl_xor_sync(0xFFFFFFFFu, s0, 2);
        s1 += __shfl_xor_sync(0xFFFFFFFFu, s1, 1);
        s1 += __shfl_xor_sync(0xFFFFFFFFu, s1, 2);
        if (tig == 0) {
            int lr0 = warp_m * 32 + mt * 16 + g;
            sm_red[warp_n][lr0] = s0;
            sm_red[warp_n][lr0 + 8] = s1;
        }
    }
    __syncthreads();
#pragma unroll
    for (int mt = 0; mt < 2; mt++) {
        int lr0 = warp_m * 32 + mt * 16 + g;
        mu[mt][0] = (sm_red[0][lr0] + sm_red[1][lr0] + sm_red[2][lr0] + sm_red[3][lr0]) / (float)NC;
        mu[mt][1] = (sm_red[0][lr0 + 8] + sm_red[1][lr0 + 8] + sm_red[2][lr0 + 8] + sm_red[3][lr0 + 8]) / (float)NC;
    }
    __syncthreads();

    // pass 2: variance of deviations
    float rstd[2][2];
#pragma unroll
    for (int mt = 0; mt < 2; mt++) {
        float s0 = 0.f, s1 = 0.f;
#pragma unroll
        for (int nt = 0; nt < NT; nt++) {
            float d0 = acc[mt][nt][0] - mu[mt][0];
            float d1 = acc[mt][nt][1] - mu[mt][0];
            float d2 = acc[mt][nt][2] - mu[mt][1];
            float d3 = acc[mt][nt][3] - mu[mt][1];
            s0 += d0 * d0 + d1 * d1;
            s1 += d2 * d2 + d3 * d3;
        }
        s0 += __shfl_xor_sync(0xFFFFFFFFu, s0, 1);
        s0 += __shfl_xor_sync(0xFFFFFFFFu, s0, 2);
        s1 += __shfl_xor_sync(0xFFFFFFFFu, s1, 1);
        s1 += __shfl_xor_sync(0xFFFFFFFFu, s1, 2);
        if (tig == 0) {
            int lr0 = warp_m * 32 + mt * 16 + g;
            sm_red[warp_n][lr0] = s0;
            sm_red[warp_n][lr0 + 8] = s1;
        }
    }
    __syncthreads();
#pragma unroll
    for (int mt = 0; mt < 2; mt++) {
        int lr0 = warp_m * 32 + mt * 16 + g;
        float v0 = (sm_red[0][lr0] + sm_red[1][lr0] + sm_red[2][lr0] + sm_red[3][lr0]) / (float)NC;
        float v1 = (sm_red[0][lr0 + 8] + sm_red[1][lr0 + 8] + sm_red[2][lr0 + 8] + sm_red[3][lr0 + 8]) / (float)NC;
        rstd[mt][0] = rsqrtf(v0 + LN_EPS);
        rstd[mt][1] = rsqrtf(v1 + LN_EPS);
    }

    // normalize + relu + write
#pragma unroll
    for (int nt = 0; nt < NT; nt++) {
        int gc = warp_n * (NC / 4) + nt * 8 + 2 * tig;
        float ga0 = gamma[gc], ga1 = gamma[gc + 1];
        float be0 = beta[gc], be1 = beta[gc + 1];
#pragma unroll
        for (int mt = 0; mt < 2; mt++) {
#pragma unroll
            for (int h = 0; h < 2; h++) {
                int gr = row0 + warp_m * 32 + mt * 16 + g + h * 8;
                if (gr >= N_NODES) continue;
                float y0 = fmaxf((acc[mt][nt][2 * h] - mu[mt][h]) * rstd[mt][h] * ga0 + be0, 0.f);
                float y1 = fmaxf((acc[mt][nt][2 * h + 1] - mu[mt][h]) * rstd[mt][h] * ga1 + be1, 0.f);
                if (outF) *(float2*)&outF[(size_t)gr * NC + gc] = make_float2(y0, y1);
                if (outH) {
                    __nv_bfloat16 h0, l0, h1, l1;
                    bf16split(y0, h0, l0);
                    bf16split(y1, h1, l1);
                    __nv_bfloat162 hp2; hp2.x = h0; hp2.y = h1;
                    __nv_bfloat162 lp2; lp2.x = l0; lp2.y = l1;
                    *(__nv_bfloat162*)&outH[(size_t)gr * KB2 + gc] = hp2;
                    *(__nv_bfloat162*)&outL[(size_t)gr * KB2 + gc] = lp2;
                }
                if (out16) {
                    __half2 hv = __floats2half2_rn(y0, y1);
                    *(__half2*)&out16[(size_t)gr * HID + gc] = hv;
                }
            }
        }
    }
}

// ---------------- launch ----------------
extern "C" void kernel_launch(void* const* d_in, const int* in_sizes, int n_in,
                              void* d_out, int out_size) {
    const float* op_feats    = (const float*)d_in[0];
    const float* config_f    = (const float*)d_in[1];
    const float* embed_table = (const float*)d_in[2];
    const float* feat_mean   = (const float*)d_in[3];
    const float* feat_std    = (const float*)d_in[4];
    const float* Wself       = (const float*)d_in[5];
    const float* Wneigh      = (const float*)d_in[6];
    const float* bconv       = (const float*)d_in[7];
    const float* conv_gamma  = (const float*)d_in[8];
    const float* conv_beta   = (const float*)d_in[9];
    const float* W1          = (const float*)d_in[10];
    const float* g1          = (const float*)d_in[11];
    const float* b1          = (const float*)d_in[12];
    const float* W2          = (const float*)d_in[13];
    const float* g2          = (const float*)d_in[14];
    const float* b2          = (const float*)d_in[15];
    const int*   op_ids      = (const int*)d_in[16];
    const int*   src         = (const int*)d_in[17];
    const int*   dst         = (const int*)d_in[18];
    float* out = (float*)d_out;

    __half* x16p;
    __nv_bfloat16 *Abh, *Abl, *WBh, *WBl, *W1h, *W1l, *W2h, *W2l;
    cudaGetSymbolAddress((void**)&x16p, g_x16);
    cudaGetSymbolAddress((void**)&Abh, g_Abh);
    cudaGetSymbolAddress((void**)&Abl, g_Abl);
    cudaGetSymbolAddress((void**)&WBh, g_WBh);
    cudaGetSymbolAddress((void**)&WBl, g_WBl);
    cudaGetSymbolAddress((void**)&W1h, g_W1h);
    cudaGetSymbolAddress((void**)&W1l, g_W1l);
    cudaGetSymbolAddress((void**)&W2h, g_W2h);
    cudaGetSymbolAddress((void**)&W2l, g_W2l);

    const int SMEM256 = 2 * (2 * BM * AS + 2 * 256 * AS) * 2;   // 102400 B
    const int SMEM128 = 2 * (2 * BM * AS + 2 * 128 * AS) * 2;   // 61440 B
    cudaFuncSetAttribute(gemm_ln_kernel<256>,
                         cudaFuncAttributeMaxDynamicSharedMemorySize, SMEM256);
    cudaFuncSetAttribute(gemm_ln_kernel<128>,
                         cudaFuncAttributeMaxDynamicSharedMemorySize, SMEM128);

    zero_kernel<<<(N_NODES + 255) / 256, 256>>>();
    deg_kernel<<<(N_EDGES + 255) / 256, 256>>>(dst);
    scan_kernel<<<1, 256>>>();
    fill_kernel<<<(N_EDGES + 255) / 256, 256>>>(src, dst);
    split_w_kernel<<<(W_TOT + 255) / 256, 256>>>(Wself, Wneigh, W1, W2);

    build_x_kernel<<<N_NODES, HID>>>(op_feats, config_f, embed_table,
                                     feat_mean, feat_std, op_ids);

    int nblk = (N_NODES + BM - 1) / BM;   // 313

    for (int i = 0; i < 4; i++) {
        agg_kernel<<<N_NODES, 64>>>();
        gemm_ln_kernel<256><<<nblk, 256, SMEM256>>>(
            Abh, Abl, KB2, WBh + i * HID * KB2, WBl + i * HID * KB2,
            bconv + i * HID, conv_gamma + i * HID, conv_beta + i * HID,
            nullptr, Abh, Abl, (i < 3) ? x16p : (__half*)nullptr, KB2);
    }

    gemm_ln_kernel<256><<<nblk, 256, SMEM256>>>(
        Abh, Abl, KB2, W1h, W1l, nullptr, g1, b1,
        nullptr, Abh, Abl, nullptr, HID);

    gemm_ln_kernel<128><<<nblk, 256, SMEM128>>>(
        Abh, Abl, KB2, W2h, W2l, nullptr, g2, b2,
        out, nullptr, nullptr, nullptr, HID);
}

// round 12
// speedup vs baseline: 1.6526x; 1.0204x over previous
#include <cuda_runtime.h>
#include <cuda_fp16.h>
#include <cuda_bf16.h>
#include <cstdint>

#define N_NODES 20000
#define N_EDGES 640000
#define HID 256
#define KB2 512
#define D_OP 140
#define D_EMB 64
#define D_CFG 52
#define LN_EPS 1e-5f

// ---------------- scratch (device globals; no allocation) ----------------
__device__ __nv_bfloat16 g_Abh[N_NODES * KB2];   // A hi: cols 0-255 = x, 256-511 = agg
__device__ __nv_bfloat16 g_Abl[N_NODES * KB2];   // A lo
__device__ __half        g_x16[N_NODES * HID];   // fp16 shadow for agg gather
__device__ __nv_bfloat16 g_WBh[4 * HID * KB2];   // [layer][n=256][k=512] transposed concat W
__device__ __nv_bfloat16 g_WBl[4 * HID * KB2];
__device__ __nv_bfloat16 g_W1h[HID * HID];       // [n=256][k=256]
__device__ __nv_bfloat16 g_W1l[HID * HID];
__device__ __nv_bfloat16 g_W2h[(HID / 2) * HID]; // [n=128][k=256]
__device__ __nv_bfloat16 g_W2l[(HID / 2) * HID];
__device__ int   g_deg[N_NODES];
__device__ float g_invdeg[N_NODES];
__device__ int   g_rowstart[N_NODES + 1];
__device__ int   g_cursor[N_NODES];
__device__ int   g_csr[N_EDGES];

__device__ __forceinline__ void bf16split(float v, __nv_bfloat16& h, __nv_bfloat16& l) {
    h = __float2bfloat16_rn(v);
    l = __float2bfloat16_rn(v - __bfloat162float(h));
}

// ---------------- graph preprocessing ----------------
__global__ void zero_kernel() {
    int i = blockIdx.x * blockDim.x + threadIdx.x;
    if (i < N_NODES) { g_deg[i] = 0; g_cursor[i] = 0; }
}

__global__ void deg_kernel(const int* __restrict__ dst) {
    int e = blockIdx.x * blockDim.x + threadIdx.x;
    if (e < N_EDGES) atomicAdd(&g_deg[dst[e]], 1);
}

__global__ void scan_kernel() {
    __shared__ int partial[256];
    int tid = threadIdx.x;
    const int CH = (N_NODES + 255) / 256;
    int base = tid * CH;
    int s = 0;
    for (int i = 0; i < CH; i++) {
        int idx = base + i;
        if (idx < N_NODES) s += g_deg[idx];
    }
    partial[tid] = s;
    __syncthreads();
    for (int off = 1; off < 256; off <<= 1) {
        int v = 0;
        if (tid >= off) v = partial[tid - off];
        __syncthreads();
        partial[tid] += v;
        __syncthreads();
    }
    int run = (tid == 0) ? 0 : partial[tid - 1];
    for (int i = 0; i < CH; i++) {
        int idx = base + i;
        if (idx < N_NODES) {
            int d = g_deg[idx];
            g_rowstart[idx] = run;
            run += d;
            g_invdeg[idx] = 1.0f / fmaxf((float)d, 1.0f);
        }
    }
    if (tid == 255) g_rowstart[N_NODES] = run;
}

__global__ void fill_kernel(const int* __restrict__ src, const int* __restrict__ dst) {
    int e = blockIdx.x * blockDim.x + threadIdx.x;
    if (e < N_EDGES) {
        int d = dst[e];
        int pos = atomicAdd(&g_cursor[d], 1);
        g_csr[g_rowstart[d] + pos] = src[e];
    }
}

// ---------------- weight transpose + bf16 split (once per launch) ----------------
#define W_LAYER (4 * HID * KB2)               // 524288
#define W_TOT (W_LAYER + HID * HID + (HID / 2) * HID)
__global__ void split_w_kernel(const float* __restrict__ Wself,
                               const float* __restrict__ Wneigh,
                               const float* __restrict__ W1,
                               const float* __restrict__ W2) {
    int i = blockIdx.x * blockDim.x + threadIdx.x;
    if (i >= W_TOT) return;
    float v; __nv_bfloat16* dh; __nv_bfloat16* dl; int di;
    if (i < W_LAYER) {
        int l = i >> 17;
        int rem = i & (HID * KB2 - 1);
        int n = rem >> 9, k = rem & 511;
        v = (k < HID) ? Wself[(l * HID + k) * HID + n]
                      : Wneigh[(l * HID + (k - HID)) * HID + n];
        dh = g_WBh; dl = g_WBl; di = i;
    } else if (i < W_LAYER + HID * HID) {
        di = i - W_LAYER;
        int n = di >> 8, k = di & 255;
        v = W1[k * HID + n];
        dh = g_W1h; dl = g_W1l;
    } else {
        di = i - (W_LAYER + HID * HID);
        int n = di >> 8, k = di & 255;
        v = W2[k * (HID / 2) + n];
        dh = g_W2h; dl = g_W2l;
    }
    bf16split(v, dh[di], dl[di]);
}

// ---------------- input feature assembly ----------------
__global__ void build_x_kernel(const float* __restrict__ op_feats,
                               const float* __restrict__ cfg,
                               const float* __restrict__ emb,
                               const float* __restrict__ fmean,
                               const float* __restrict__ fstd,
                               const int* __restrict__ op_ids) {
    int n = blockIdx.x;
    int c = threadIdx.x;
    float v;
    if (c < D_OP)               v = op_feats[n * D_OP + c];
    else if (c < D_OP + D_EMB)  v = emb[op_ids[n] * D_EMB + (c - D_OP)];
    else                        v = cfg[n * D_CFG + (c - D_OP - D_EMB)];
    float xv = (v - fmean[c]) / fstd[c];
    bf16split(xv, g_Abh[n * KB2 + c], g_Abl[n * KB2 + c]);
    g_x16[n * HID + c] = __float2half(xv);
}

// ---------------- neighbor mean aggregation: 32 threads/node, uint4 loads ----------------
__device__ __forceinline__ void acc8(float* a, const uint4& r) {
    float2 p0 = __half22float2(*(const __half2*)&r.x);
    float2 p1 = __half22float2(*(const __half2*)&r.y);
    float2 p2 = __half22float2(*(const __half2*)&r.z);
    float2 p3 = __half22float2(*(const __half2*)&r.w);
    a[0] += p0.x; a[1] += p0.y; a[2] += p1.x; a[3] += p1.y;
    a[4] += p2.x; a[5] += p2.y; a[6] += p3.x; a[7] += p3.y;
}

__global__ __launch_bounds__(128) void agg_kernel() {
    int n = blockIdx.x * 4 + (threadIdx.x >> 5);
    if (n >= N_NODES) return;
    int t = threadIdx.x & 31;   // 32 threads/node, each owns 8 channels (uint4)
    int s0 = g_rowstart[n], s1 = g_rowstart[n + 1];
    const uint4* __restrict__ xv = (const uint4*)g_x16;   // 32 uint4 per row

    float a[8];
#pragma unroll
    for (int i = 0; i < 8; i++) a[i] = 0.f;

    int j = s0;
    for (; j + 4 <= s1; j += 4) {
        int i0 = g_csr[j], i1 = g_csr[j + 1], i2 = g_csr[j + 2], i3 = g_csr[j + 3];
        uint4 r0 = xv[i0 * 32 + t];
        uint4 r1 = xv[i1 * 32 + t];
        uint4 r2 = xv[i2 * 32 + t];
        uint4 r3 = xv[i3 * 32 + t];
        acc8(a, r0); acc8(a, r1); acc8(a, r2); acc8(a, r3);
    }
    for (; j < s1; j++) {
        uint4 r = xv[g_csr[j] * 32 + t];
        acc8(a, r);
    }
    float id = g_invdeg[n];
    __nv_bfloat16 hh[8], ll[8];
#pragma unroll
    for (int i = 0; i < 8; i++) bf16split(a[i] * id, hh[i], ll[i]);
    // cols 256 + t*8 .. +7 of row n (16 bytes each)
    *(uint4*)&g_Abh[n * KB2 + HID + t * 8] = *(const uint4*)hh;
    *(uint4*)&g_Abl[n * KB2 + HID + t * 8] = *(const uint4*)ll;
}

// ---------------- fused bf16x3 GEMM + LayerNorm + ReLU ----------------
// One CTA computes FULL rows: BM=64 rows x NC cols. 8 warps = 2m x 4n.
#define BM 64
#define AS 40   // halves per smem row (80B, LDSM conflict-free)

__device__ __forceinline__ uint32_t sm_u32(const void* p) {
    uint32_t a;
    asm("{ .reg .u64 t; cvta.to.shared.u64 t, %1; cvt.u32.u64 %0, t; }" : "=r"(a) : "l"(p));
    return a;
}
__device__ __forceinline__ void cp16(uint32_t d, const void* s) {
    asm volatile("cp.async.cg.shared.global [%0], [%1], 16;" :: "r"(d), "l"(s));
}
__device__ __forceinline__ void cp16z(uint32_t d, const void* s, int sz) {
    asm volatile("cp.async.cg.shared.global [%0], [%1], 16, %2;" :: "r"(d), "l"(s), "r"(sz));
}
__device__ __forceinline__ void ldsm4(uint32_t* r, uint32_t addr) {
    asm volatile("ldmatrix.sync.aligned.m8n8.x4.shared.b16 {%0,%1,%2,%3}, [%4];"
        : "=r"(r[0]), "=r"(r[1]), "=r"(r[2]), "=r"(r[3]) : "r"(addr));
}
__device__ __forceinline__ void mma_bf16(float* c, const uint32_t* a, const uint32_t* b) {
    asm volatile(
        "mma.sync.aligned.m16n8k16.row.col.f32.bf16.bf16.f32 "
        "{%0,%1,%2,%3}, {%4,%5,%6,%7}, {%8,%9}, {%0,%1,%2,%3};"
        : "+f"(c[0]), "+f"(c[1]), "+f"(c[2]), "+f"(c[3])
        : "r"(a[0]), "r"(a[1]), "r"(a[2]), "r"(a[3]), "r"(b[0]), "r"(b[1]));
}

template <int NC>
__global__ __launch_bounds__(256) void gemm_ln_kernel(
    const __nv_bfloat16* __restrict__ Agh, const __nv_bfloat16* __restrict__ Agl, int lda,
    const __nv_bfloat16* __restrict__ Bgh, const __nv_bfloat16* __restrict__ Bgl,
    const float* __restrict__ bias,
    const float* __restrict__ gamma, const float* __restrict__ beta,
    float* __restrict__ outF,                 // stride NC (may be null)
    __nv_bfloat16* __restrict__ outH,         // stride KB2 (may be null)
    __nv_bfloat16* __restrict__ outL,
    __half* __restrict__ out16,               // stride HID (may be null)
    int K)
{
    constexpr int NT = NC / 32;               // n8-fragment count per warp
    constexpr int ASH = 0;
    constexpr int ASL = BM * AS;              // 2560
    constexpr int BSH = 2 * BM * AS;          // 5120
    constexpr int BSL = 2 * BM * AS + NC * AS;
    constexpr int STAGE = 2 * BM * AS + 2 * NC * AS;   // halves
    constexpr int NB = NC / 64;               // B chunks per thread per array

    extern __shared__ uint16_t smem[];
    __shared__ float sm_red[4][BM];
    uint32_t s_base = sm_u32(smem);

    int tid = threadIdx.x;
    int lane = tid & 31, wid = tid >> 5;
    int warp_m = wid & 1, warp_n = wid >> 1;  // 2m x 4n
    int g = lane >> 2, tig = lane & 3;
    int lt = lane >> 3, lr = lane & 7;

    int row0 = blockIdx.x * BM;

    // A copy map: 64 rows x 4 chunks = 256 chunks; 1 per thread (hi+lo)
    int am = tid >> 2, ak = (tid & 3) * 8;
    // B copy map: NC rows x 4 chunks; NB per thread (hi+lo each)
    int bn_[NB], bk_[NB];
#pragma unroll
    for (int r = 0; r < NB; r++) {
        int c = tid + 256 * r;
        bn_[r] = c >> 2;
        bk_[r] = (c & 3) * 8;
    }

    float acc[2][NT][4];
#pragma unroll
    for (int mt = 0; mt < 2; mt++)
#pragma unroll
        for (int nt = 0; nt < NT; nt++)
#pragma unroll
            for (int i = 0; i < 4; i++) acc[mt][nt][i] = 0.f;

    const int NIT = K / 32;

    auto ISSUE = [&](int it, int buf) {
        int k0 = it * 32;
        uint32_t st = s_base + buf * (STAGE * 2);
        {
            int gm = row0 + am;
            int cgm = (gm < N_NODES) ? gm : (N_NODES - 1);
            int sz = (gm < N_NODES) ? 16 : 0;
            size_t off = (size_t)cgm * lda + k0 + ak;
            uint32_t so = (am * AS + ak) * 2;
            cp16z(st + ASH * 2 + so, Agh + off, sz);
            cp16z(st + ASL * 2 + so, Agl + off, sz);
        }
#pragma unroll
        for (int r = 0; r < NB; r++) {
            size_t off = (size_t)bn_[r] * K + k0 + bk_[r];
            uint32_t so = (bn_[r] * AS + bk_[r]) * 2;
            cp16(st + BSH * 2 + so, Bgh + off);
            cp16(st + BSL * 2 + so, Bgl + off);
        }
        asm volatile("cp.async.commit_group;");
    };

    auto COMPUTE = [&](int buf) {
        uint32_t st = s_base + buf * (STAGE * 2);
#pragma unroll
        for (int ks = 0; ks < 2; ks++) {
            int k0 = ks * 16;
            uint32_t ah[2][4], al[2][4], bh[NT][2], bl[NT][2];
#pragma unroll
            for (int mt = 0; mt < 2; mt++) {
                int row = warp_m * 32 + mt * 16 + (lt & 1) * 8 + lr;
                int col = k0 + (lt >> 1) * 8;
                uint32_t off = (uint32_t)(row * AS + col) * 2;
                ldsm4(ah[mt], st + ASH * 2 + off);
                ldsm4(al[mt], st + ASL * 2 + off);
            }
#pragma unroll
            for (int p = 0; p < NT / 2; p++) {
                int nr = warp_n * (NC / 4) + p * 16 + (lt >> 1) * 8 + lr;
                int col = k0 + (lt & 1) * 8;
                uint32_t off = (uint32_t)(nr * AS + col) * 2;
                uint32_t t[4];
                ldsm4(t, st + BSH * 2 + off);
                bh[2 * p][0] = t[0]; bh[2 * p][1] = t[1];
                bh[2 * p + 1][0] = t[2]; bh[2 * p + 1][1] = t[3];
                ldsm4(t, st + BSL * 2 + off);
                bl[2 * p][0] = t[0]; bl[2 * p][1] = t[1];
                bl[2 * p + 1][0] = t[2]; bl[2 * p + 1][1] = t[3];
            }
#pragma unroll
            for (int mt = 0; mt < 2; mt++)
#pragma unroll
                for (int nt = 0; nt < NT; nt++) {
                    mma_bf16(acc[mt][nt], ah[mt], bh[nt]);
                    mma_bf16(acc[mt][nt], al[mt], bh[nt]);
                    mma_bf16(acc[mt][nt], ah[mt], bl[nt]);
                }
        }
    };

    ISSUE(0, 0);
    int buf = 0;
    for (int it = 0; it < NIT; it++) {
        if (it + 1 < NIT) {
            ISSUE(it + 1, buf ^ 1);
            asm volatile("cp.async.wait_group 1;");
        } else {
            asm volatile("cp.async.wait_group 0;");
        }
        __syncthreads();
        COMPUTE(buf);
        __syncthreads();
        buf ^= 1;
    }

    // ---------------- fused epilogue: bias + LayerNorm + ReLU + writes ----------------
#pragma unroll
    for (int nt = 0; nt < NT; nt++) {
        int gc = warp_n * (NC / 4) + nt * 8 + 2 * tig;
        float b0 = bias ? bias[gc] : 0.f;
        float b1 = bias ? bias[gc + 1] : 0.f;
#pragma unroll
        for (int mt = 0; mt < 2; mt++) {
            acc[mt][nt][0] += b0; acc[mt][nt][1] += b1;
            acc[mt][nt][2] += b0; acc[mt][nt][3] += b1;
        }
    }

    // pass 1: row sums -> mean
    float mu[2][2];
#pragma unroll
    for (int mt = 0; mt < 2; mt++) {
        float s0 = 0.f, s1 = 0.f;
#pragma unroll
        for (int nt = 0; nt < NT; nt++) {
            s0 += acc[mt][nt][0] + acc[mt][nt][1];
            s1 += acc[mt][nt][2] + acc[mt][nt][3];
        }
        s0 += __shfl_xor_sync(0xFFFFFFFFu, s0, 1);
        s0 += __shfl_xor_sync(0xFFFFFFFFu, s0, 2);
        s1 += __shfl_xor_sync(0xFFFFFFFFu, s1, 1);
        s1 += __shfl_xor_sync(0xFFFFFFFFu, s1, 2);
        if (tig == 0) {
            int lr0 = warp_m * 32 + mt * 16 + g;
            sm_red[warp_n][lr0] = s0;
            sm_red[warp_n][lr0 + 8] = s1;
        }
    }
    __syncthreads();
#pragma unroll
    for (int mt = 0; mt < 2; mt++) {
        int lr0 = warp_m * 32 + mt * 16 + g;
        mu[mt][0] = (sm_red[0][lr0] + sm_red[1][lr0] + sm_red[2][lr0] + sm_red[3][lr0]) / (float)NC;
        mu[mt][1] = (sm_red[0][lr0 + 8] + sm_red[1][lr0 + 8] + sm_red[2][lr0 + 8] + sm_red[3][lr0 + 8]) / (float)NC;
    }
    __syncthreads();

    // pass 2: variance of deviations
    float rstd[2][2];
#pragma unroll
    for (int mt = 0; mt < 2; mt++) {
        float s0 = 0.f, s1 = 0.f;
#pragma unroll
        for (int nt = 0; nt < NT; nt++) {
            float d0 = acc[mt][nt][0] - mu[mt][0];
            float d1 = acc[mt][nt][1] - mu[mt][0];
            float d2 = acc[mt][nt][2] - mu[mt][1];
            float d3 = acc[mt][nt][3] - mu[mt][1];
            s0 += d0 * d0 + d1 * d1;
            s1 += d2 * d2 + d3 * d3;
        }
        s0 += __shfl_xor_sync(0xFFFFFFFFu, s0, 1);
        s0 += __shfl_xor_sync(0xFFFFFFFFu, s0, 2);
        s1 += __shfl_xor_sync(0xFFFFFFFFu, s1, 1);
        s1 += __shfl_xor_sync(0xFFFFFFFFu, s1, 2);
        if (tig == 0) {
            int lr0 = warp_m * 32 + mt * 16 + g;
            sm_red[warp_n][lr0] = s0;
            sm_red[warp_n][lr0 + 8] = s1;
        }
    }
    __syncthreads();
#pragma unroll
    for (int mt = 0; mt < 2; mt++) {
        int lr0 = warp_m * 32 + mt * 16 + g;
        float v0 = (sm_red[0][lr0] + sm_red[1][lr0] + sm_red[2][lr0] + sm_red[3][lr0]) / (float)NC;
        float v1 = (sm_red[0][lr0 + 8] + sm_red[1][lr0 + 8] + sm_red[2][lr0 + 8] + sm_red[3][lr0 + 8]) / (float)NC;
        rstd[mt][0] = rsqrtf(v0 + LN_EPS);
        rstd[mt][1] = rsqrtf(v1 + LN_EPS);
    }

    // normalize + relu + write
#pragma unroll
    for (int nt = 0; nt < NT; nt++) {
        int gc = warp_n * (NC / 4) + nt * 8 + 2 * tig;
        float ga0 = gamma[gc], ga1 = gamma[gc + 1];
        float be0 = beta[gc], be1 = beta[gc + 1];
#pragma unroll
        for (int mt = 0; mt < 2; mt++) {
#pragma unroll
            for (int h = 0; h < 2; h++) {
                int gr = row0 + warp_m * 32 + mt * 16 + g + h * 8;
                if (gr >= N_NODES) continue;
                float y0 = fmaxf((acc[mt][nt][2 * h] - mu[mt][h]) * rstd[mt][h] * ga0 + be0, 0.f);
                float y1 = fmaxf((acc[mt][nt][2 * h + 1] - mu[mt][h]) * rstd[mt][h] * ga1 + be1, 0.f);
                if (outF) *(float2*)&outF[(size_t)gr * NC + gc] = make_float2(y0, y1);
                if (outH) {
                    __nv_bfloat16 h0, l0, h1, l1;
                    bf16split(y0, h0, l0);
                    bf16split(y1, h1, l1);
                    __nv_bfloat162 hp2; hp2.x = h0; hp2.y = h1;
                    __nv_bfloat162 lp2; lp2.x = l0; lp2.y = l1;
                    *(__nv_bfloat162*)&outH[(size_t)gr * KB2 + gc] = hp2;
                    *(__nv_bfloat162*)&outL[(size_t)gr * KB2 + gc] = lp2;
                }
                if (out16) {
                    __half2 hv = __floats2half2_rn(y0, y1);
                    *(__half2*)&out16[(size_t)gr * HID + gc] = hv;
                }
            }
        }
    }
}

// ---------------- launch ----------------
extern "C" void kernel_launch(void* const* d_in, const int* in_sizes, int n_in,
                              void* d_out, int out_size) {
    const float* op_feats    = (const float*)d_in[0];
    const float* config_f    = (const float*)d_in[1];
    const float* embed_table = (const float*)d_in[2];
    const float* feat_mean   = (const float*)d_in[3];
    const float* feat_std    = (const float*)d_in[4];
    const float* Wself       = (const float*)d_in[5];
    const float* Wneigh      = (const float*)d_in[6];
    const float* bconv       = (const float*)d_in[7];
    const float* conv_gamma  = (const float*)d_in[8];
    const float* conv_beta   = (const float*)d_in[9];
    const float* W1          = (const float*)d_in[10];
    const float* g1          = (const float*)d_in[11];
    const float* b1          = (const float*)d_in[12];
    const float* W2          = (const float*)d_in[13];
    const float* g2          = (const float*)d_in[14];
    const float* b2          = (const float*)d_in[15];
    const int*   op_ids      = (const int*)d_in[16];
    const int*   src         = (const int*)d_in[17];
    const int*   dst         = (const int*)d_in[18];
    float* out = (float*)d_out;

    __half* x16p;
    __nv_bfloat16 *Abh, *Abl, *WBh, *WBl, *W1h, *W1l, *W2h, *W2l;
    cudaGetSymbolAddress((void**)&x16p, g_x16);
    cudaGetSymbolAddress((void**)&Abh, g_Abh);
    cudaGetSymbolAddress((void**)&Abl, g_Abl);
    cudaGetSymbolAddress((void**)&WBh, g_WBh);
    cudaGetSymbolAddress((void**)&WBl, g_WBl);
    cudaGetSymbolAddress((void**)&W1h, g_W1h);
    cudaGetSymbolAddress((void**)&W1l, g_W1l);
    cudaGetSymbolAddress((void**)&W2h, g_W2h);
    cudaGetSymbolAddress((void**)&W2l, g_W2l);

    const int SMEM256 = 2 * (2 * BM * AS + 2 * 256 * AS) * 2;   // 102400 B
    const int SMEM128 = 2 * (2 * BM * AS + 2 * 128 * AS) * 2;   // 61440 B
    cudaFuncSetAttribute(gemm_ln_kernel<256>,
                         cudaFuncAttributeMaxDynamicSharedMemorySize, SMEM256);
    cudaFuncSetAttribute(gemm_ln_kernel<128>,
                         cudaFuncAttributeMaxDynamicSharedMemorySize, SMEM128);

    zero_kernel<<<(N_NODES + 255) / 256, 256>>>();
    deg_kernel<<<(N_EDGES + 255) / 256, 256>>>(dst);
    scan_kernel<<<1, 256>>>();
    fill_kernel<<<(N_EDGES + 255) / 256, 256>>>(src, dst);
    split_w_kernel<<<(W_TOT + 255) / 256, 256>>>(Wself, Wneigh, W1, W2);

    build_x_kernel<<<N_NODES, HID>>>(op_feats, config_f, embed_table,
                                     feat_mean, feat_std, op_ids);

    int nblk = (N_NODES + BM - 1) / BM;            // 313
    int ablk = (N_NODES + 3) / 4;                  // 5000

    for (int i = 0; i < 4; i++) {
        agg_kernel<<<ablk, 128>>>();
        gemm_ln_kernel<256><<<nblk, 256, SMEM256>>>(
            Abh, Abl, KB2, WBh + i * HID * KB2, WBl + i * HID * KB2,
            bconv + i * HID, conv_gamma + i * HID, conv_beta + i * HID,
            nullptr, Abh, Abl, (i < 3) ? x16p : (__half*)nullptr, KB2);
    }

    gemm_ln_kernel<256><<<nblk, 256, SMEM256>>>(
        Abh, Abl, KB2, W1h, W1l, nullptr, g1, b1,
        nullptr, Abh, Abl, nullptr, HID);

    gemm_ln_kernel<128><<<nblk, 256, SMEM128>>>(
        Abh, Abl, KB2, W2h, W2l, nullptr, g2, b2,
        out, nullptr, nullptr, nullptr, HID);
}

// round 13
// speedup vs baseline: 2.1938x; 1.3275x over previous
#include <cuda_runtime.h>
#include <cuda_fp16.h>
#include <cuda_bf16.h>
#include <cstdint>

#define N_NODES 20000
#define N_EDGES 640000
#define HID 256
#define KB2 512
#define D_OP 140
#define D_EMB 64
#define D_CFG 52
#define LN_EPS 1e-5f

// ---------------- scratch (device globals; no allocation) ----------------
// A matrix fp16 hi/lo: cols 0-255 = x, 256-511 = agg. Agg gathers read hi cols 0-255.
__device__ __half g_Abh[N_NODES * KB2];
__device__ __half g_Abl[N_NODES * KB2];
__device__ __half g_WBh[4 * HID * KB2];   // [layer][n=256][k=512] transposed concat W (fp16)
__device__ __half g_W1h[HID * HID];       // [n=256][k=256]
__device__ __half g_W2h[(HID / 2) * HID]; // [n=128][k=256]
__device__ int   g_deg[N_NODES];
__device__ float g_invdeg[N_NODES];
__device__ int   g_rowstart[N_NODES + 1];
__device__ int   g_cursor[N_NODES];
__device__ int   g_csr[N_EDGES];

__device__ __forceinline__ void f16split(float v, __half& h, __half& l) {
    h = __float2half_rn(v);
    l = __float2half_rn(v - __half2float(h));
}

// ---------------- graph preprocessing ----------------
__global__ void zero_kernel() {
    int i = blockIdx.x * blockDim.x + threadIdx.x;
    if (i < N_NODES) { g_deg[i] = 0; g_cursor[i] = 0; }
}

__global__ void deg_kernel(const int* __restrict__ dst) {
    int e = blockIdx.x * blockDim.x + threadIdx.x;
    if (e < N_EDGES) atomicAdd(&g_deg[dst[e]], 1);
}

__global__ void scan_kernel() {
    __shared__ int partial[256];
    int tid = threadIdx.x;
    const int CH = (N_NODES + 255) / 256;
    int base = tid * CH;
    int s = 0;
    for (int i = 0; i < CH; i++) {
        int idx = base + i;
        if (idx < N_NODES) s += g_deg[idx];
    }
    partial[tid] = s;
    __syncthreads();
    for (int off = 1; off < 256; off <<= 1) {
        int v = 0;
        if (tid >= off) v = partial[tid - off];
        __syncthreads();
        partial[tid] += v;
        __syncthreads();
    }
    int run = (tid == 0) ? 0 : partial[tid - 1];
    for (int i = 0; i < CH; i++) {
        int idx = base + i;
        if (idx < N_NODES) {
            int d = g_deg[idx];
            g_rowstart[idx] = run;
            run += d;
            g_invdeg[idx] = 1.0f / fmaxf((float)d, 1.0f);
        }
    }
    if (tid == 255) g_rowstart[N_NODES] = run;
}

__global__ void fill_kernel(const int* __restrict__ src, const int* __restrict__ dst) {
    int e = blockIdx.x * blockDim.x + threadIdx.x;
    if (e < N_EDGES) {
        int d = dst[e];
        int pos = atomicAdd(&g_cursor[d], 1);
        g_csr[g_rowstart[d] + pos] = src[e];
    }
}

// ---------------- weight transpose + fp16 round (once per launch) ----------------
#define W_LAYER (4 * HID * KB2)               // 524288
#define W_TOT (W_LAYER + HID * HID + (HID / 2) * HID)
__global__ void split_w_kernel(const float* __restrict__ Wself,
                               const float* __restrict__ Wneigh,
                               const float* __restrict__ W1,
                               const float* __restrict__ W2) {
    int i = blockIdx.x * blockDim.x + threadIdx.x;
    if (i >= W_TOT) return;
    float v; __half* dh; int di;
    if (i < W_LAYER) {
        int l = i >> 17;
        int rem = i & (HID * KB2 - 1);
        int n = rem >> 9, k = rem & 511;
        v = (k < HID) ? Wself[(l * HID + k) * HID + n]
                      : Wneigh[(l * HID + (k - HID)) * HID + n];
        dh = g_WBh; di = i;
    } else if (i < W_LAYER + HID * HID) {
        di = i - W_LAYER;
        int n = di >> 8, k = di & 255;
        v = W1[k * HID + n];
        dh = g_W1h;
    } else {
        di = i - (W_LAYER + HID * HID);
        int n = di >> 8, k = di & 255;
        v = W2[k * (HID / 2) + n];
        dh = g_W2h;
    }
    dh[di] = __float2half_rn(v);
}

// ---------------- input feature assembly ----------------
__global__ void build_x_kernel(const float* __restrict__ op_feats,
                               const float* __restrict__ cfg,
                               const float* __restrict__ emb,
                               const float* __restrict__ fmean,
                               const float* __restrict__ fstd,
                               const int* __restrict__ op_ids) {
    int n = blockIdx.x;
    int c = threadIdx.x;
    float v;
    if (c < D_OP)               v = op_feats[n * D_OP + c];
    else if (c < D_OP + D_EMB)  v = emb[op_ids[n] * D_EMB + (c - D_OP)];
    else                        v = cfg[n * D_CFG + (c - D_OP - D_EMB)];
    float xv = (v - fmean[c]) / fstd[c];
    f16split(xv, g_Abh[n * KB2 + c], g_Abl[n * KB2 + c]);
}

// ---------------- neighbor mean aggregation: gather x-hi cols from A matrix ----------------
__device__ __forceinline__ void acc8(float* a, const uint4& r) {
    float2 p0 = __half22float2(*(const __half2*)&r.x);
    float2 p1 = __half22float2(*(const __half2*)&r.y);
    float2 p2 = __half22float2(*(const __half2*)&r.z);
    float2 p3 = __half22float2(*(const __half2*)&r.w);
    a[0] += p0.x; a[1] += p0.y; a[2] += p1.x; a[3] += p1.y;
    a[4] += p2.x; a[5] += p2.y; a[6] += p3.x; a[7] += p3.y;
}

__global__ __launch_bounds__(128) void agg_kernel() {
    int n = blockIdx.x * 4 + (threadIdx.x >> 5);
    if (n >= N_NODES) return;
    int t = threadIdx.x & 31;   // 32 threads/node, each owns 8 channels (uint4)
    int s0 = g_rowstart[n], s1 = g_rowstart[n + 1];
    const uint4* __restrict__ xv = (const uint4*)g_Abh;   // 64 uint4 per row; x = first 32

    float a[8];
#pragma unroll
    for (int i = 0; i < 8; i++) a[i] = 0.f;

    int j = s0;
    for (; j + 4 <= s1; j += 4) {
        int i0 = g_csr[j], i1 = g_csr[j + 1], i2 = g_csr[j + 2], i3 = g_csr[j + 3];
        uint4 r0 = xv[i0 * 64 + t];
        uint4 r1 = xv[i1 * 64 + t];
        uint4 r2 = xv[i2 * 64 + t];
        uint4 r3 = xv[i3 * 64 + t];
        acc8(a, r0); acc8(a, r1); acc8(a, r2); acc8(a, r3);
    }
    for (; j < s1; j++) {
        uint4 r = xv[g_csr[j] * 64 + t];
        acc8(a, r);
    }
    float id = g_invdeg[n];
    __half hh[8], ll[8];
#pragma unroll
    for (int i = 0; i < 8; i++) f16split(a[i] * id, hh[i], ll[i]);
    *(uint4*)&g_Abh[n * KB2 + HID + t * 8] = *(const uint4*)hh;
    *(uint4*)&g_Abl[n * KB2 + HID + t * 8] = *(const uint4*)ll;
}

// ---------------- fused fp16x2 GEMM + LayerNorm + ReLU ----------------
// C = (Ah + Al) @ Bh^T; one CTA owns BM=64 full rows x NC cols. 8 warps = 2m x 4n.
#define BM 64
#define AS 40   // halves per smem row (80B, LDSM conflict-free)

__device__ __forceinline__ uint32_t sm_u32(const void* p) {
    uint32_t a;
    asm("{ .reg .u64 t; cvta.to.shared.u64 t, %1; cvt.u32.u64 %0, t; }" : "=r"(a) : "l"(p));
    return a;
}
__device__ __forceinline__ void cp16(uint32_t d, const void* s) {
    asm volatile("cp.async.cg.shared.global [%0], [%1], 16;" :: "r"(d), "l"(s));
}
__device__ __forceinline__ void cp16z(uint32_t d, const void* s, int sz) {
    asm volatile("cp.async.cg.shared.global [%0], [%1], 16, %2;" :: "r"(d), "l"(s), "r"(sz));
}
__device__ __forceinline__ void ldsm4(uint32_t* r, uint32_t addr) {
    asm volatile("ldmatrix.sync.aligned.m8n8.x4.shared.b16 {%0,%1,%2,%3}, [%4];"
        : "=r"(r[0]), "=r"(r[1]), "=r"(r[2]), "=r"(r[3]) : "r"(addr));
}
__device__ __forceinline__ void mma_f16(float* c, const uint32_t* a, const uint32_t* b) {
    asm volatile(
        "mma.sync.aligned.m16n8k16.row.col.f32.f16.f16.f32 "
        "{%0,%1,%2,%3}, {%4,%5,%6,%7}, {%8,%9}, {%0,%1,%2,%3};"
        : "+f"(c[0]), "+f"(c[1]), "+f"(c[2]), "+f"(c[3])
        : "r"(a[0]), "r"(a[1]), "r"(a[2]), "r"(a[3]), "r"(b[0]), "r"(b[1]));
}

template <int NC>
__global__ __launch_bounds__(256) void gemm_ln_kernel(
    const __half* __restrict__ Agh, const __half* __restrict__ Agl, int lda,
    const __half* __restrict__ Bgh,
    const float* __restrict__ bias,
    const float* __restrict__ gamma, const float* __restrict__ beta,
    float* __restrict__ outF,           // stride NC (may be null)
    __half* __restrict__ outH,          // stride KB2 (may be null)
    __half* __restrict__ outL,
    int K)
{
    constexpr int NT = NC / 32;
    constexpr int ASH = 0;
    constexpr int ASL = BM * AS;              // 2560
    constexpr int BSH = 2 * BM * AS;          // 5120
    constexpr int STAGE = 2 * BM * AS + NC * AS;   // halves
    constexpr int NB = NC / 64;               // B chunks per thread

    extern __shared__ uint16_t smem[];
    __shared__ float sm_red[4][BM];
    uint32_t s_base = sm_u32(smem);

    int tid = threadIdx.x;
    int lane = tid & 31, wid = tid >> 5;
    int warp_m = wid & 1, warp_n = wid >> 1;  // 2m x 4n
    int g = lane >> 2, tig = lane & 3;
    int lt = lane >> 3, lr = lane & 7;

    int row0 = blockIdx.x * BM;

    // A copy map: 64 rows x 4 chunks = 256 chunks; 1 per thread (hi+lo)
    int am = tid >> 2, ak = (tid & 3) * 8;
    // B copy map: NC rows x 4 chunks; NB per thread (hi only)
    int bn_[NB], bk_[NB];
#pragma unroll
    for (int r = 0; r < NB; r++) {
        int c = tid + 256 * r;
        bn_[r] = c >> 2;
        bk_[r] = (c & 3) * 8;
    }

    float acc[2][NT][4];
#pragma unroll
    for (int mt = 0; mt < 2; mt++)
#pragma unroll
        for (int nt = 0; nt < NT; nt++)
#pragma unroll
            for (int i = 0; i < 4; i++) acc[mt][nt][i] = 0.f;

    const int NIT = K / 32;

    auto ISSUE = [&](int it, int buf) {
        int k0 = it * 32;
        uint32_t st = s_base + buf * (STAGE * 2);
        {
            int gm = row0 + am;
            int cgm = (gm < N_NODES) ? gm : (N_NODES - 1);
            int sz = (gm < N_NODES) ? 16 : 0;
            size_t off = (size_t)cgm * lda + k0 + ak;
            uint32_t so = (am * AS + ak) * 2;
            cp16z(st + ASH * 2 + so, Agh + off, sz);
            cp16z(st + ASL * 2 + so, Agl + off, sz);
        }
#pragma unroll
        for (int r = 0; r < NB; r++) {
            size_t off = (size_t)bn_[r] * K + k0 + bk_[r];
            uint32_t so = (bn_[r] * AS + bk_[r]) * 2;
            cp16(st + BSH * 2 + so, Bgh + off);
        }
        asm volatile("cp.async.commit_group;");
    };

    auto COMPUTE = [&](int buf) {
        uint32_t st = s_base + buf * (STAGE * 2);
#pragma unroll
        for (int ks = 0; ks < 2; ks++) {
            int k0 = ks * 16;
            uint32_t ah[2][4], al[2][4], bh[NT][2];
#pragma unroll
            for (int mt = 0; mt < 2; mt++) {
                int row = warp_m * 32 + mt * 16 + (lt & 1) * 8 + lr;
                int col = k0 + (lt >> 1) * 8;
                uint32_t off = (uint32_t)(row * AS + col) * 2;
                ldsm4(ah[mt], st + ASH * 2 + off);
                ldsm4(al[mt], st + ASL * 2 + off);
            }
#pragma unroll
            for (int p = 0; p < NT / 2; p++) {
                int nr = warp_n * (NC / 4) + p * 16 + (lt >> 1) * 8 + lr;
                int col = k0 + (lt & 1) * 8;
                uint32_t off = (uint32_t)(nr * AS + col) * 2;
                uint32_t t[4];
                ldsm4(t, st + BSH * 2 + off);
                bh[2 * p][0] = t[0]; bh[2 * p][1] = t[1];
                bh[2 * p + 1][0] = t[2]; bh[2 * p + 1][1] = t[3];
            }
#pragma unroll
            for (int mt = 0; mt < 2; mt++)
#pragma unroll
                for (int nt = 0; nt < NT; nt++) {
                    mma_f16(acc[mt][nt], ah[mt], bh[nt]);
                    mma_f16(acc[mt][nt], al[mt], bh[nt]);
                }
        }
    };

    ISSUE(0, 0);
    int buf = 0;
    for (int it = 0; it < NIT; it++) {
        if (it + 1 < NIT) {
            ISSUE(it + 1, buf ^ 1);
            asm volatile("cp.async.wait_group 1;");
        } else {
            asm volatile("cp.async.wait_group 0;");
        }
        __syncthreads();
        COMPUTE(buf);
        __syncthreads();
        buf ^= 1;
    }

    // ---------------- fused epilogue: bias + LayerNorm + ReLU + writes ----------------
#pragma unroll
    for (int nt = 0; nt < NT; nt++) {
        int gc = warp_n * (NC / 4) + nt * 8 + 2 * tig;
        float b0 = bias ? bias[gc] : 0.f;
        float b1 = bias ? bias[gc + 1] : 0.f;
#pragma unroll
        for (int mt = 0; mt < 2; mt++) {
            acc[mt][nt][0] += b0; acc[mt][nt][1] += b1;
            acc[mt][nt][2] += b0; acc[mt][nt][3] += b1;
        }
    }

    // pass 1: row sums -> mean
    float mu[2][2];
#pragma unroll
    for (int mt = 0; mt < 2; mt++) {
        float s0 = 0.f, s1 = 0.f;
#pragma unroll
        for (int nt = 0; nt < NT; nt++) {
            s0 += acc[mt][nt][0] + acc[mt][nt][1];
            s1 += acc[mt][nt][2] + acc[mt][nt][3];
        }
        s0 += __shfl_xor_sync(0xFFFFFFFFu, s0, 1);
        s0 += __shfl_xor_sync(0xFFFFFFFFu, s0, 2);
        s1 += __shfl_xor_sync(0xFFFFFFFFu, s1, 1);
        s1 += __shfl_xor_sync(0xFFFFFFFFu, s1, 2);
        if (tig == 0) {
            int lr0 = warp_m * 32 + mt * 16 + g;
            sm_red[warp_n][lr0] = s0;
            sm_red[warp_n][lr0 + 8] = s1;
        }
    }
    __syncthreads();
#pragma unroll
    for (int mt = 0; mt < 2; mt++) {
        int lr0 = warp_m * 32 + mt * 16 + g;
        mu[mt][0] = (sm_red[0][lr0] + sm_red[1][lr0] + sm_red[2][lr0] + sm_red[3][lr0]) / (float)NC;
        mu[mt][1] = (sm_red[0][lr0 + 8] + sm_red[1][lr0 + 8] + sm_red[2][lr0 + 8] + sm_red[3][lr0 + 8]) / (float)NC;
    }
    __syncthreads();

    // pass 2: variance of deviations
    float rstd[2][2];
#pragma unroll
    for (int mt = 0; mt < 2; mt++) {
        float s0 = 0.f, s1 = 0.f;
#pragma unroll
        for (int nt = 0; nt < NT; nt++) {
            float d0 = acc[mt][nt][0] - mu[mt][0];
            float d1 = acc[mt][nt][1] - mu[mt][0];
            float d2 = acc[mt][nt][2] - mu[mt][1];
            float d3 = acc[mt][nt][3] - mu[mt][1];
            s0 += d0 * d0 + d1 * d1;
            s1 += d2 * d2 + d3 * d3;
        }
        s0 += __shfl_xor_sync(0xFFFFFFFFu, s0, 1);
        s0 += __shfl_xor_sync(0xFFFFFFFFu, s0, 2);
        s1 += __shfl_xor_sync(0xFFFFFFFFu, s1, 1);
        s1 += __shfl_xor_sync(0xFFFFFFFFu, s1, 2);
        if (tig == 0) {
            int lr0 = warp_m * 32 + mt * 16 + g;
            sm_red[warp_n][lr0] = s0;
            sm_red[warp_n][lr0 + 8] = s1;
        }
    }
    __syncthreads();
#pragma unroll
    for (int mt = 0; mt < 2; mt++) {
        int lr0 = warp_m * 32 + mt * 16 + g;
        float v0 = (sm_red[0][lr0] + sm_red[1][lr0] + sm_red[2][lr0] + sm_red[3][lr0]) / (float)NC;
        float v1 = (sm_red[0][lr0 + 8] + sm_red[1][lr0 + 8] + sm_red[2][lr0 + 8] + sm_red[3][lr0 + 8]) / (float)NC;
        rstd[mt][0] = rsqrtf(v0 + LN_EPS);
        rstd[mt][1] = rsqrtf(v1 + LN_EPS);
    }

    // normalize + relu + write
#pragma unroll
    for (int nt = 0; nt < NT; nt++) {
        int gc = warp_n * (NC / 4) + nt * 8 + 2 * tig;
        float ga0 = gamma[gc], ga1 = gamma[gc + 1];
        float be0 = beta[gc], be1 = beta[gc + 1];
#pragma unroll
        for (int mt = 0; mt < 2; mt++) {
#pragma unroll
            for (int h = 0; h < 2; h++) {
                int gr = row0 + warp_m * 32 + mt * 16 + g + h * 8;
                if (gr >= N_NODES) continue;
                float y0 = fmaxf((acc[mt][nt][2 * h] - mu[mt][h]) * rstd[mt][h] * ga0 + be0, 0.f);
                float y1 = fmaxf((acc[mt][nt][2 * h + 1] - mu[mt][h]) * rstd[mt][h] * ga1 + be1, 0.f);
                if (outF) *(float2*)&outF[(size_t)gr * NC + gc] = make_float2(y0, y1);
                if (outH) {
                    __half h0, l0, h1, l1;
                    f16split(y0, h0, l0);
                    f16split(y1, h1, l1);
                    __half2 hp2; hp2.x = h0; hp2.y = h1;
                    __half2 lp2; lp2.x = l0; lp2.y = l1;
                    *(__half2*)&outH[(size_t)gr * KB2 + gc] = hp2;
                    *(__half2*)&outL[(size_t)gr * KB2 + gc] = lp2;
                }
            }
        }
    }
}

// ---------------- launch ----------------
extern "C" void kernel_launch(void* const* d_in, const int* in_sizes, int n_in,
                              void* d_out, int out_size) {
    const float* op_feats    = (const float*)d_in[0];
    const float* config_f    = (const float*)d_in[1];
    const float* embed_table = (const float*)d_in[2];
    const float* feat_mean   = (const float*)d_in[3];
    const float* feat_std    = (const float*)d_in[4];
    const float* Wself       = (const float*)d_in[5];
    const float* Wneigh      = (const float*)d_in[6];
    const float* bconv       = (const float*)d_in[7];
    const float* conv_gamma  = (const float*)d_in[8];
    const float* conv_beta   = (const float*)d_in[9];
    const float* W1          = (const float*)d_in[10];
    const float* g1          = (const float*)d_in[11];
    const float* b1          = (const float*)d_in[12];
    const float* W2          = (const float*)d_in[13];
    const float* g2          = (const float*)d_in[14];
    const float* b2          = (const float*)d_in[15];
    const int*   op_ids      = (const int*)d_in[16];
    const int*   src         = (const int*)d_in[17];
    const int*   dst         = (const int*)d_in[18];
    float* out = (float*)d_out;

    __half *Abh, *Abl, *WBh, *W1h, *W2h;
    cudaGetSymbolAddress((void**)&Abh, g_Abh);
    cudaGetSymbolAddress((void**)&Abl, g_Abl);
    cudaGetSymbolAddress((void**)&WBh, g_WBh);
    cudaGetSymbolAddress((void**)&W1h, g_W1h);
    cudaGetSymbolAddress((void**)&W2h, g_W2h);

    const int SMEM256 = 2 * (2 * BM * AS + 256 * AS) * 2;   // 61440 B
    const int SMEM128 = 2 * (2 * BM * AS + 128 * AS) * 2;   // 40960 B
    cudaFuncSetAttribute(gemm_ln_kernel<256>,
                         cudaFuncAttributeMaxDynamicSharedMemorySize, SMEM256);
    cudaFuncSetAttribute(gemm_ln_kernel<128>,
                         cudaFuncAttributeMaxDynamicSharedMemorySize, SMEM128);

    zero_kernel<<<(N_NODES + 255) / 256, 256>>>();
    deg_kernel<<<(N_EDGES + 255) / 256, 256>>>(dst);
    scan_kernel<<<1, 256>>>();
    fill_kernel<<<(N_EDGES + 255) / 256, 256>>>(src, dst);
    split_w_kernel<<<(W_TOT + 255) / 256, 256>>>(Wself, Wneigh, W1, W2);

    build_x_kernel<<<N_NODES, HID>>>(op_feats, config_f, embed_table,
                                     feat_mean, feat_std, op_ids);

    int nblk = (N_NODES + BM - 1) / BM;            // 313
    int ablk = (N_NODES + 3) / 4;                  // 5000

    for (int i = 0; i < 4; i++) {
        agg_kernel<<<ablk, 128>>>();
        gemm_ln_kernel<256><<<nblk, 256, SMEM256>>>(
            Abh, Abl, KB2, WBh + i * HID * KB2,
            bconv + i * HID, conv_gamma + i * HID, conv_beta + i * HID,
            nullptr, Abh, Abl, KB2);
    }

    gemm_ln_kernel<256><<<nblk, 256, SMEM256>>>(
        Abh, Abl, KB2, W1h, nullptr, g1, b1,
        nullptr, Abh, Abl, HID);

    gemm_ln_kernel<128><<<nblk, 256, SMEM128>>>(
        Abh, Abl, KB2, W2h, nullptr, g2, b2,
        out, nullptr, nullptr, HID);
}